// round 14
// baseline (speedup 1.0000x reference)
#include <cuda_runtime.h>
#include <math.h>
#include <stdint.h>

#define TT 2048
#define DD 1024
#define EE 8
#define NI 1023
#define KD 1024

#define ROWS_ROUTED (EE * TT)
#define SHARED_BASE ROWS_ROUTED
#define TOTAL_ROWS  (ROWS_ROUTED + TT)

#if defined(__CUDA_ARCH_FEAT_SM103_ALL) || defined(__CUDA_ARCH_FEAT_SM100_ALL) || defined(__CUDA_ARCH_FEAT_SM101_ALL)
#define HAS_TCGEN05 1
#else
#define HAS_TCGEN05 0
#endif

// ------------------- device scratch -------------------
__device__ float g_H[(size_t)TOTAL_ROWS * KD];
__device__ float g_O[(size_t)TOTAL_ROWS * KD];
__device__ float g_part1[(size_t)TOTAL_ROWS * 16];
__device__ float g_part2[(size_t)TOTAL_ROWS * 16];
__device__ int   g_cnt[EE];
__device__ int   g_bucket[ROWS_ROUTED];
__device__ int   g_rowOf[TT];
__device__ float g_wgt[TT];

// ------------------------------ helpers -----------------------------------------
__device__ __forceinline__ uint32_t smem_to_u32(const void* p) {
    uint32_t a;
    asm("{ .reg .u64 t; cvta.to.shared.u64 t, %1; cvt.u32.u64 %0, t; }" : "=r"(a) : "l"(p));
    return a;
}
__device__ __forceinline__ uint32_t f2tf32(float f) {
    uint32_t o; asm("cvt.rna.tf32.f32 %0, %1;" : "=r"(o) : "f"(f)); return o;
}
__device__ __forceinline__ float silu_mul(float v1, float v3) {
    return v1 * v3 / (1.0f + __expf(-v1));
}
__device__ __forceinline__ void cp_async16(uint32_t smem_addr, const void* gptr, uint32_t src_size) {
    asm volatile("cp.async.cg.shared.global [%0], [%1], 16, %2;"
                 :: "r"(smem_addr), "l"(gptr), "r"(src_size) : "memory");
}
#define CP_COMMIT() asm volatile("cp.async.commit_group;" ::: "memory")
#define CP_WAIT2()  asm volatile("cp.async.wait_group 2;" ::: "memory")
#define CP_WAIT3()  asm volatile("cp.async.wait_group 3;" ::: "memory")
#define CP_WAIT1()  asm volatile("cp.async.wait_group 1;" ::: "memory")

#define MBARRIER_INIT(mbar, count) \
    asm volatile("mbarrier.init.shared.b64 [%0], %1;" \
        :: "r"((uint32_t)(mbar)), "r"((uint32_t)(count)) : "memory")
#define MBARRIER_WAIT_PARITY(mbar_smem_addr, phase_parity) do { \
    uint32_t _mbar = (uint32_t)(mbar_smem_addr); \
    uint32_t _parity = (uint32_t)(phase_parity); \
    uint32_t _done; \
    asm volatile("{\n\t.reg .pred p;\n\t" \
        "mbarrier.try_wait.parity.acquire.cta.shared::cta.b64 p, [%1], %2;\n\t" \
        "selp.b32 %0, 1, 0, p;\n\t}" : "=r"(_done) : "r"(_mbar), "r"(_parity) : "memory"); \
    if (!_done) { \
        asm volatile("{\n\t.reg .pred P1;\n\t" \
            "WAIT_LOOP_%=:\n\t" \
            "mbarrier.try_wait.parity.acquire.cta.shared::cta.b64 P1, [%0], %1, 0x989680;\n\t" \
            "@P1 bra.uni WAIT_DONE_%=;\n\t" \
            "bra.uni WAIT_LOOP_%=;\n\t" \
            "WAIT_DONE_%=:\n\t}" :: "r"(_mbar), "r"(_parity) : "memory"); \
    } \
} while(0)

#if HAS_TCGEN05
__device__ __forceinline__ uint32_t elect_one_pred() {
    uint32_t pred;
    asm volatile("{\n\t.reg .pred p;\n\telect.sync _|p, 0xFFFFFFFF;\n\t"
                 "selp.b32 %0, 1, 0, p;\n\t}" : "=r"(pred));
    return pred;
}
#define TCGEN05_ALLOC(smem_result_addr, nCols) \
    asm volatile("tcgen05.alloc.cta_group::1.sync.aligned.shared::cta.b32 [%0], %1;" \
        :: "r"((uint32_t)(smem_result_addr)), "r"((uint32_t)(nCols)) : "memory")
#define TCGEN05_DEALLOC(tmem_addr, nCols) \
    asm volatile("tcgen05.dealloc.cta_group::1.sync.aligned.b32 %0, %1;" \
        :: "r"(tmem_addr), "r"((uint32_t)(nCols)))
#define TCGEN05_COMMIT(mbar_smem_addr) \
    asm volatile("tcgen05.commit.cta_group::1.mbarrier::arrive::one.shared::cluster.b64 [%0];" \
        :: "r"((uint32_t)(mbar_smem_addr)) : "memory")
#define TCGEN05_WAIT_LD() asm volatile("tcgen05.wait::ld.sync.aligned;" ::: "memory")
#define TCGEN05_FENCE_AFTER() asm volatile("tcgen05.fence::after_thread_sync;" ::: "memory")
#define FENCE_PROXY_ASYNC_SHARED_CTA() asm volatile("fence.proxy.async.shared::cta;" ::: "memory")
#define TCGEN05_LD_32X32B_X32(r, tmem_addr) \
    asm volatile("tcgen05.ld.sync.aligned.32x32b.x32.b32 " \
        "{%0, %1, %2, %3, %4, %5, %6, %7, " \
        " %8, %9, %10, %11, %12, %13, %14, %15, " \
        " %16, %17, %18, %19, %20, %21, %22, %23, " \
        " %24, %25, %26, %27, %28, %29, %30, %31}, [%32];" \
        : "=r"((r)[0]),  "=r"((r)[1]),  "=r"((r)[2]),  "=r"((r)[3]), \
          "=r"((r)[4]),  "=r"((r)[5]),  "=r"((r)[6]),  "=r"((r)[7]), \
          "=r"((r)[8]),  "=r"((r)[9]),  "=r"((r)[10]), "=r"((r)[11]), \
          "=r"((r)[12]), "=r"((r)[13]), "=r"((r)[14]), "=r"((r)[15]), \
          "=r"((r)[16]), "=r"((r)[17]), "=r"((r)[18]), "=r"((r)[19]), \
          "=r"((r)[20]), "=r"((r)[21]), "=r"((r)[22]), "=r"((r)[23]), \
          "=r"((r)[24]), "=r"((r)[25]), "=r"((r)[26]), "=r"((r)[27]), \
          "=r"((r)[28]), "=r"((r)[29]), "=r"((r)[30]), "=r"((r)[31]) \
        : "r"(tmem_addr))

static constexpr uint64_t SMEM_DESC_BASE_SW128 =
    (uint64_t(2) << 61) | (uint64_t(1) << 46) | (uint64_t(64) << 32) | (uint64_t(1) << 16);
#define MAKE_SMEM_DESC(base_addr) \
    (SMEM_DESC_BASE_SW128 | ((uint64_t)((base_addr) >> 4) & 0x3FFF))
#define IDESC_TF32_N128 ((1u<<4) | (2u<<7) | (2u<<10) | (16u<<17) | (8u<<24))

__device__ __forceinline__ void mma_tf32_ss(uint32_t d_tmem, uint64_t a_desc,
                                            uint64_t b_desc, uint32_t idesc, bool acc) {
    uint32_t en = acc ? 1u : 0u;
    asm volatile(
        "{\n\t.reg .pred p;\n\tsetp.ne.u32 p, %5, 0;\n\t"
        "tcgen05.mma.cta_group::1.kind::tf32 [%0], %1, %2, %3, {%4, %4, %4, %4}, p;\n\t}"
        :: "r"(d_tmem), "l"(a_desc), "l"(b_desc), "r"(idesc), "r"(0u), "r"(en)
        : "memory");
}
#endif // HAS_TCGEN05

#define MMA_TF32_SYNC(d, a, b) \
    asm volatile("mma.sync.aligned.m16n8k8.row.col.f32.tf32.tf32.f32 " \
        "{%0,%1,%2,%3}, {%4,%5,%6,%7}, {%8,%9}, {%0,%1,%2,%3};" \
        : "+f"((d)[0]), "+f"((d)[1]), "+f"((d)[2]), "+f"((d)[3]) \
        : "r"((a)[0]), "r"((a)[1]), "r"((a)[2]), "r"((a)[3]), \
          "r"((b)[0]), "r"((b)[1]))

// ------------------------------- small kernels ----------------------------------
__device__ __forceinline__ float warp_reduce_sum(float v) {
    #pragma unroll
    for (int o = 16; o; o >>= 1) v += __shfl_xor_sync(0xffffffffu, v, o);
    return v;
}

__global__ void zero_cnt_kernel() {
    if (threadIdx.x < EE) g_cnt[threadIdx.x] = 0;
}

__global__ void dummy_kernel() {}

__global__ void gate_kernel(const float* __restrict__ x,
                            const float* __restrict__ gate_w,
                            const float* __restrict__ gate_b) {
    int tid = threadIdx.x;
    int w = tid >> 5, lane = tid & 31;
    __shared__ float sl[8][8];

    float gw_reg[32];
    const float* gr = gate_w + (size_t)w * NI;
    #pragma unroll
    for (int i = 0; i < 32; i++) {
        int c = lane + 32 * i;
        gw_reg[i] = (c < NI) ? gr[c] : 0.0f;
    }
    #pragma unroll
    for (int j = 0; j < 8; j++) {
        int t = blockIdx.x * 8 + j;
        const float* xr = x + (size_t)t * DD + 1;
        float s = 0.0f;
        #pragma unroll
        for (int i = 0; i < 32; i++) {
            int c = lane + 32 * i;
            if (c < NI) s += gw_reg[i] * xr[c];
        }
        s = warp_reduce_sum(s);
        if (lane == 0) sl[j][w] = s;
    }
    __syncthreads();
    if (tid < 8) {
        int t = blockIdx.x * 8 + tid;
        float m = sl[tid][0];
        #pragma unroll
        for (int e = 1; e < EE; e++) m = fmaxf(m, sl[tid][e]);
        float ex[EE], den = 0.0f;
        #pragma unroll
        for (int e = 0; e < EE; e++) { ex[e] = expf(sl[tid][e] - m); den += ex[e]; }
        float inv = 1.0f / den;
        float best = -1e30f; int bi = 0;
        #pragma unroll
        for (int e = 0; e < EE; e++) {
            float biased = ex[e] * inv + gate_b[e];
            if (biased > best) { best = biased; bi = e; }
        }
        g_wgt[t] = ex[bi] * inv;
        int p = atomicAdd(&g_cnt[bi], 1);
        g_bucket[bi * TT + p] = t;
        g_rowOf[t] = bi * TT + p;
    }
}

__global__ void norm_kernel(int which) {
    int gid = blockIdx.x * 256 + threadIdx.x;
    if (gid >= 2 * TT) return;
    int row = (gid < TT) ? g_rowOf[gid] : (SHARED_BASE + (gid - TT));
    const float* pp = (which ? g_part2 : g_part1) + (size_t)row * 16;
    float s = 1.0f;
    #pragma unroll
    for (int j = 0; j < 16; j++) s += pp[j];
    (which ? g_O : g_H)[(size_t)row * KD] = sqrtf(s);
}

__global__ void combine_kernel(float* __restrict__ out) {
    int lane = threadIdx.x & 31;
    int t = blockIdx.x * 8 + (threadIdx.x >> 5);
    int rr = g_rowOf[t];
    float wgt = g_wgt[t];
    const float* zr = g_O + (size_t)(SHARED_BASE + t) * KD;
    const float* er = g_O + (size_t)rr * KD;
    float comb[32];
    float ss = 0.0f;
    #pragma unroll
    for (int i = 0; i < 32; i++) {
        int d = lane + 32 * i;
        float y = (d == 0) ? (1.0f + wgt * er[0]) : (wgt * er[d]);
        float cv = zr[d] + 2.0f * y;
        comb[i] = cv;
        if (d != 0) ss += cv * cv;
    }
    ss = warp_reduce_sum(ss);
    float c0 = __shfl_sync(0xffffffffu, comb[0], 0);
    float li = ss - c0 * c0;
    float scale = rsqrtf(fmaxf(fabsf(li), 1e-8f));
    #pragma unroll
    for (int i = 0; i < 32; i++)
        out[(size_t)t * DD + lane + 32 * i] = comb[i] * scale;
}

// ------------------------------ smem layout --------------------------------------
#define SM_TOKS  0
#define SM_MBAR  512
#define SM_TMEMP 528
#define SM_BUF   1024
#define TILE16K  16384
#define T1_STAGE (3 * TILE16K)
#define T2_STAGE (2 * TILE16K)
#define SMEM1_TOTAL (SM_BUF + 4 * T1_STAGE)   // 197632 : 4 buffers, depth-3
#define SMEM2_TOTAL (SM_BUF + 6 * T2_STAGE)   // 197632 : 6 buffers, depth-4, wait c-2
#define NCHUNK 32

// fallback layout constants (non-'a' pass only)
#define ASTR   36
#define F_A_BYTES (128 * ASTR * 4)
#define F_B_BYTES (64  * ASTR * 4)
#define F1_STAGE (F_A_BYTES + 2 * F_B_BYTES)
#define F2_STAGE (F_A_BYTES + F_B_BYTES)

// ------------------------------ GEMM 1 ------------------------------------------
__global__ void __launch_bounds__(256) gemm1_tc(
    const float* __restrict__ x,
    const float* __restrict__ W1, const float* __restrict__ W3,
    const float* __restrict__ Ws1, const float* __restrict__ Ws3)
{
    extern __shared__ char smem[];
    int tid = threadIdx.x;
    int wid = tid >> 5;

    int e = blockIdx.z;
    int cnt; const float *w1p, *w3p; int rowBase;
    if (e < EE) {
        cnt = g_cnt[e];
        w1p = W1 + (size_t)e * NI * KD;
        w3p = W3 + (size_t)e * NI * KD;
        rowBase = e * TT;
    } else {
        cnt = TT; w1p = Ws1; w3p = Ws3; rowBase = SHARED_BASE;
    }
    int m0 = blockIdx.y * 128;
    if (m0 >= cnt) return;

#if HAS_TCGEN05
    if (blockIdx.x & 1) return;
    int n0 = (blockIdx.x >> 1) * 128;
    uint32_t sb = smem_to_u32(smem);

    int* toks = (int*)(smem + SM_TOKS);
    if (tid < 128) {
        int p = m0 + tid;
        toks[tid] = (p < cnt) ? ((e < EE) ? g_bucket[e * TT + p] : p) : -1;
    }
    if (wid == 0) TCGEN05_ALLOC(sb + SM_TMEMP, 256);
    if (tid == 0) { MBARRIER_INIT(sb + SM_MBAR, 1); MBARRIER_INIT(sb + SM_MBAR + 8, 1); }
    __syncthreads();
    uint32_t tmem;
    asm volatile("ld.shared.b32 %0, [%1];" : "=r"(tmem) : "r"(sb + SM_TMEMP));

    uint32_t l_sw[4];
    const float* a_gp[4]; uint32_t a_sz[4];
    const float* b1_gp[4]; const float* b3_gp[4]; uint32_t b_sz[4];
    #pragma unroll
    for (int i = 0; i < 4; i++) {
        int idx = tid + i * 256;
        int r = idx >> 3, c4 = idx & 7;
        uint32_t off = (uint32_t)(r * 128 + c4 * 16);
        l_sw[i] = off ^ ((off >> 3) & 0x70);
        int tok = toks[r];
        a_sz[i] = (tok >= 0) ? 16u : 0u;
        a_gp[i] = x + ((tok >= 0) ? ((size_t)tok * DD + c4 * 4) : 0);
        int n = n0 + r;
        b_sz[i] = (n < NI) ? 16u : 0u;
        size_t boff = (n < NI) ? ((size_t)n * KD + c4 * 4) : 0;
        b1_gp[i] = w1p + boff;
        b3_gp[i] = w3p + boff;
    }

    auto issue_stage = [&](int c) {
        uint32_t base = sb + SM_BUF + (c & 3) * T1_STAGE;
        int k0 = c * 32;
        #pragma unroll
        for (int i = 0; i < 4; i++) {
            cp_async16(base + l_sw[i],                a_gp[i] + k0, a_sz[i]);
            cp_async16(base + TILE16K + l_sw[i],      b1_gp[i] + k0, b_sz[i]);
            cp_async16(base + 2 * TILE16K + l_sw[i],  b3_gp[i] + k0, b_sz[i]);
        }
        CP_COMMIT();
    };

    issue_stage(0); issue_stage(1); issue_stage(2);

    for (int c = 0; c < NCHUNK; c++) {
        CP_WAIT2();
        __syncthreads();
        if (wid == 0) {
            if (elect_one_pred()) {
                FENCE_PROXY_ASYNC_SHARED_CTA();
                uint32_t base = sb + SM_BUF + (c & 3) * T1_STAGE;
                uint64_t ad  = MAKE_SMEM_DESC(base);
                uint64_t b1d = MAKE_SMEM_DESC(base + TILE16K);
                uint64_t b3d = MAKE_SMEM_DESC(base + 2 * TILE16K);
                #pragma unroll
                for (int k = 0; k < 4; k++) {
                    bool acc = (c > 0) || (k > 0);
                    mma_tf32_ss(tmem,       ad + k*2, b1d + k*2, IDESC_TF32_N128, acc);
                    mma_tf32_ss(tmem + 128, ad + k*2, b3d + k*2, IDESC_TF32_N128, acc);
                }
                TCGEN05_COMMIT(sb + SM_MBAR + 8 * (c & 1));
            }
        }
        if (c >= 1)
            MBARRIER_WAIT_PARITY(sb + SM_MBAR + 8 * ((c - 1) & 1), ((c - 1) >> 1) & 1);
        if (c + 3 < NCHUNK) issue_stage(c + 3);
        else CP_COMMIT();
    }
    MBARRIER_WAIT_PARITY(sb + SM_MBAR + 8, 1);   // chunk 31
    __syncthreads();
    TCGEN05_FENCE_AFTER();

    // Epilogue: sp = silu(d1)*d3 with fused row-partials of sp^2
    float* st = (float*)(smem + SM_BUF);
    float psum = 0.0f;
    for (int cb = 0; cb < 128; cb += 32) {
        if (tid < 128) {
            uint32_t d1[32], d2[32];
            TCGEN05_LD_32X32B_X32(d1, tmem + cb);
            TCGEN05_LD_32X32B_X32(d2, tmem + 128 + cb);
            TCGEN05_WAIT_LD();
            #pragma unroll
            for (int j = 0; j < 32; j++) {
                float sp = silu_mul(__uint_as_float(d1[j]), __uint_as_float(d2[j]));
                st[tid * 33 + j] = sp;
                psum += sp * sp;
            }
        }
        __syncthreads();
        #pragma unroll
        for (int i = 0; i < 16; i++) {
            int l = tid + i * 256;
            int r = l >> 5, cc = l & 31;
            int p = m0 + r;
            int col = n0 + cb + cc;
            if (p < cnt && col < NI)
                g_H[(size_t)(rowBase + p) * KD + 1 + col] = st[r * 33 + cc];
        }
        __syncthreads();
    }
    if (tid < 128) {
        int p = m0 + tid;
        if (p < cnt) {
            int slot = n0 >> 6;
            g_part1[(size_t)(rowBase + p) * 16 + slot]     = psum;
            g_part1[(size_t)(rowBase + p) * 16 + slot + 1] = 0.0f;
        }
    }
    if (wid == 0) TCGEN05_DEALLOC(tmem, 256);
#else
    // ---------------- fallback: pipelined mma.sync (compute_103 pass only) --------
    int n0 = blockIdx.x * 64;
    int* toks = (int*)smem;
    uint32_t sbuf = smem_to_u32(smem) + 1024;
    __shared__ float s_ps[128];
    if (tid < 128) {
        int p = m0 + tid;
        toks[tid] = (p < cnt) ? ((e < EE) ? g_bucket[e * TT + p] : p) : -1;
        s_ps[tid] = 0.0f;
    }
    __syncthreads();
    int a_r[4], a_c4[4], a_tok[4];
    #pragma unroll
    for (int i = 0; i < 4; i++) {
        int idx = tid + i * 256;
        a_r[i] = idx >> 3; a_c4[i] = idx & 7; a_tok[i] = toks[a_r[i]];
    }
    int b_r[2], b_c4[2];
    #pragma unroll
    for (int i = 0; i < 2; i++) {
        int idx = tid + i * 256;
        b_r[i] = idx >> 3; b_c4[i] = idx & 7;
    }
    auto issue_stage = [&](int c) {
        int buf = c % 3;
        uint32_t aB  = sbuf + buf * F1_STAGE;
        uint32_t b1B = aB + F_A_BYTES;
        uint32_t b3B = b1B + F_B_BYTES;
        int k0 = c * 32;
        #pragma unroll
        for (int i = 0; i < 4; i++) {
            int tok = a_tok[i];
            const float* src = x + ((tok >= 0) ? ((size_t)tok * DD + k0 + a_c4[i] * 4) : 0);
            cp_async16(aB + (a_r[i] * ASTR + a_c4[i] * 4) * 4, src, (tok >= 0) ? 16u : 0u);
        }
        #pragma unroll
        for (int i = 0; i < 2; i++) {
            int n = n0 + b_r[i];
            bool bv = (n < NI);
            size_t off = bv ? ((size_t)n * KD + k0 + b_c4[i] * 4) : 0;
            uint32_t so = (b_r[i] * ASTR + b_c4[i] * 4) * 4;
            cp_async16(b1B + so, w1p + off, bv ? 16u : 0u);
            cp_async16(b3B + so, w3p + off, bv ? 16u : 0u);
        }
        CP_COMMIT();
    };
    int lane = tid & 31, grp = lane >> 2, tig = lane & 3;
    int mbase = (wid & 3) * 32, nbase = (wid >> 2) * 32;
    float c1[2][4][4], c3[2][4][4];
    #pragma unroll
    for (int mt = 0; mt < 2; mt++)
        #pragma unroll
        for (int nt = 0; nt < 4; nt++)
            #pragma unroll
            for (int q = 0; q < 4; q++) { c1[mt][nt][q] = 0.f; c3[mt][nt][q] = 0.f; }
    issue_stage(0); issue_stage(1);
    for (int c = 0; c < NCHUNK; c++) {
        CP_WAIT1();
        __syncthreads();
        if (c + 2 < NCHUNK) issue_stage(c + 2);
        else CP_COMMIT();
        int buf = c % 3;
        const float* As  = (const float*)(smem + 1024 + buf * F1_STAGE);
        const float* B1s = As + 128 * ASTR;
        const float* B3s = B1s + 64 * ASTR;
        #pragma unroll
        for (int ks = 0; ks < 4; ks++) {
            int kk = ks * 8;
            uint32_t a[2][4];
            #pragma unroll
            for (int mt = 0; mt < 2; mt++) {
                int r0 = mbase + mt * 16 + grp;
                a[mt][0] = f2tf32(As[r0 * ASTR + kk + tig]);
                a[mt][1] = f2tf32(As[(r0 + 8) * ASTR + kk + tig]);
                a[mt][2] = f2tf32(As[r0 * ASTR + kk + tig + 4]);
                a[mt][3] = f2tf32(As[(r0 + 8) * ASTR + kk + tig + 4]);
            }
            uint32_t b1[4][2], b3[4][2];
            #pragma unroll
            for (int nt = 0; nt < 4; nt++) {
                int cr = nbase + nt * 8 + grp;
                b1[nt][0] = f2tf32(B1s[cr * ASTR + kk + tig]);
                b1[nt][1] = f2tf32(B1s[cr * ASTR + kk + tig + 4]);
                b3[nt][0] = f2tf32(B3s[cr * ASTR + kk + tig]);
                b3[nt][1] = f2tf32(B3s[cr * ASTR + kk + tig + 4]);
            }
            #pragma unroll
            for (int mt = 0; mt < 2; mt++)
                #pragma unroll
                for (int nt = 0; nt < 4; nt++) {
                    MMA_TF32_SYNC(c1[mt][nt], a[mt], b1[nt]);
                    MMA_TF32_SYNC(c3[mt][nt], a[mt], b3[nt]);
                }
        }
        __syncthreads();
    }
    #pragma unroll
    for (int mt = 0; mt < 2; mt++) {
        int pr = mbase + mt * 16 + grp;
        #pragma unroll
        for (int nt = 0; nt < 4; nt++) {
            int col = n0 + nbase + nt * 8 + 2 * tig;
            int p = m0 + pr;
            if (p < cnt) {
                float* hrow = g_H + (size_t)(rowBase + p) * KD + 1;
                float s0 = silu_mul(c1[mt][nt][0], c3[mt][nt][0]);
                float s1 = silu_mul(c1[mt][nt][1], c3[mt][nt][1]);
                float add = 0.f;
                if (col < NI)     { hrow[col]     = s0; add += s0 * s0; }
                if (col + 1 < NI) { hrow[col + 1] = s1; add += s1 * s1; }
                atomicAdd(&s_ps[pr], add);
            }
            int p2 = p + 8;
            if (p2 < cnt) {
                float* hrow = g_H + (size_t)(rowBase + p2) * KD + 1;
                float s2 = silu_mul(c1[mt][nt][2], c3[mt][nt][2]);
                float s3 = silu_mul(c1[mt][nt][3], c3[mt][nt][3]);
                float add = 0.f;
                if (col < NI)     { hrow[col]     = s2; add += s2 * s2; }
                if (col + 1 < NI) { hrow[col + 1] = s3; add += s3 * s3; }
                atomicAdd(&s_ps[pr + 8], add);
            }
        }
    }
    __syncthreads();
    if (tid < 128) {
        int p = m0 + tid;
        if (p < cnt) g_part1[(size_t)(rowBase + p) * 16 + (n0 >> 6)] = s_ps[tid];
    }
#endif
}

// ------------------------------ GEMM 2 ------------------------------------------
// 6 buffers, issue distance 4, relaxed MMA wait (chunk c-2).
__global__ void __launch_bounds__(256) gemm2_tc(
    const float* __restrict__ W2, const float* __restrict__ Ws2)
{
    extern __shared__ char smem[];
    int tid = threadIdx.x;
    int wid = tid >> 5;

    int e = blockIdx.z;
    int cnt; const float* wp; int rowBase;
    if (e < EE) { cnt = g_cnt[e]; wp = W2 + (size_t)e * NI * KD; rowBase = e * TT; }
    else        { cnt = TT;       wp = Ws2;                      rowBase = SHARED_BASE; }
    int m0 = blockIdx.y * 128;
    if (m0 >= cnt) return;

#if HAS_TCGEN05
    if (blockIdx.x & 1) return;
    int n0 = (blockIdx.x >> 1) * 128;
    uint32_t sb = smem_to_u32(smem);

    if (wid == 0) TCGEN05_ALLOC(sb + SM_TMEMP, 128);
    if (tid == 0) { MBARRIER_INIT(sb + SM_MBAR, 1); MBARRIER_INIT(sb + SM_MBAR + 8, 1); }
    __syncthreads();
    uint32_t tmem;
    asm volatile("ld.shared.b32 %0, [%1];" : "=r"(tmem) : "r"(sb + SM_TMEMP));

    uint32_t l_sw[4];
    const float* a_gp[4]; uint32_t a_sz[4];
    const float* b_gp[4]; uint32_t b_sz[4];
    #pragma unroll
    for (int i = 0; i < 4; i++) {
        int idx = tid + i * 256;
        int r = idx >> 3, c4 = idx & 7;
        uint32_t off = (uint32_t)(r * 128 + c4 * 16);
        l_sw[i] = off ^ ((off >> 3) & 0x70);
        int p = m0 + r;
        a_sz[i] = (p < cnt) ? 16u : 0u;
        a_gp[i] = g_H + ((p < cnt) ? ((size_t)(rowBase + p) * KD + c4 * 4) : 0);
        int n = n0 + r;
        b_sz[i] = (n < NI) ? 16u : 0u;
        b_gp[i] = wp + ((n < NI) ? ((size_t)n * KD + c4 * 4) : 0);
    }

    auto issue_stage = [&](int c) {
        uint32_t base = sb + SM_BUF + (c % 6) * T2_STAGE;
        int k0 = c * 32;
        #pragma unroll
        for (int i = 0; i < 4; i++) {
            cp_async16(base + l_sw[i],           a_gp[i] + k0, a_sz[i]);
            cp_async16(base + TILE16K + l_sw[i], b_gp[i] + k0, b_sz[i]);
        }
        CP_COMMIT();
    };

    issue_stage(0); issue_stage(1); issue_stage(2); issue_stage(3);

    for (int c = 0; c < NCHUNK; c++) {
        CP_WAIT3();                 // stage c complete (c+1..c+3 may be in flight)
        __syncthreads();
        if (wid == 0) {
            if (elect_one_pred()) {
                FENCE_PROXY_ASYNC_SHARED_CTA();
                uint32_t base = sb + SM_BUF + (c % 6) * T2_STAGE;
                uint64_t ad = MAKE_SMEM_DESC(base);
                uint64_t bd = MAKE_SMEM_DESC(base + TILE16K);
                #pragma unroll
                for (int k = 0; k < 4; k++) {
                    bool acc = (c > 0) || (k > 0);
                    mma_tf32_ss(tmem, ad + k*2, bd + k*2, IDESC_TF32_N128, acc);
                }
                TCGEN05_COMMIT(sb + SM_MBAR + 8 * (c & 1));
            }
        }
        // relaxed wait: buffer (c+4)%6 == (c-2)%6 was read by MMA chunk c-2,
        // whose commit happened two iterations ago -> fast-path most of the time.
        if (c >= 2)
            MBARRIER_WAIT_PARITY(sb + SM_MBAR + 8 * ((c - 2) & 1), ((c - 2) >> 1) & 1);
        if (c + 4 < NCHUNK) issue_stage(c + 4);
        else CP_COMMIT();
    }
    // in-loop consumed chunks 0..29 in order; finish 30, then 31 (next phases per mbar)
    MBARRIER_WAIT_PARITY(sb + SM_MBAR,     1);   // chunk 30 (mbar0 phase 15)
    MBARRIER_WAIT_PARITY(sb + SM_MBAR + 8, 1);   // chunk 31 (mbar1 phase 15)
    __syncthreads();
    TCGEN05_FENCE_AFTER();

    float* st = (float*)(smem + SM_BUF);
    float psum = 0.0f;
    for (int cb = 0; cb < 128; cb += 32) {
        if (tid < 128) {
            uint32_t d[32];
            TCGEN05_LD_32X32B_X32(d, tmem + cb);
            TCGEN05_WAIT_LD();
            #pragma unroll
            for (int j = 0; j < 32; j++) {
                float v = __uint_as_float(d[j]);
                st[tid * 33 + j] = v;
                psum += v * v;
            }
        }
        __syncthreads();
        #pragma unroll
        for (int i = 0; i < 16; i++) {
            int l = tid + i * 256;
            int r = l >> 5, cc = l & 31;
            int p = m0 + r;
            int col = n0 + cb + cc;
            if (p < cnt && col < NI)
                g_O[(size_t)(rowBase + p) * KD + 1 + col] = st[r * 33 + cc];
        }
        __syncthreads();
    }
    if (tid < 128) {
        int p = m0 + tid;
        if (p < cnt) {
            int slot = n0 >> 6;
            g_part2[(size_t)(rowBase + p) * 16 + slot]     = psum;
            g_part2[(size_t)(rowBase + p) * 16 + slot + 1] = 0.0f;
        }
    }
    if (wid == 0) TCGEN05_DEALLOC(tmem, 128);
#else
    int n0 = blockIdx.x * 64;
    uint32_t sbuf = smem_to_u32(smem) + 1024;
    __shared__ float s_ps[128];
    if (tid < 128) s_ps[tid] = 0.0f;
    __syncthreads();
    int a_r[4], a_c4[4];
    bool a_v[4];
    const float* a_src[4];
    #pragma unroll
    for (int i = 0; i < 4; i++) {
        int idx = tid + i * 256;
        a_r[i] = idx >> 3; a_c4[i] = idx & 7;
        int p = m0 + a_r[i];
        a_v[i] = (p < cnt);
        a_src[i] = g_H + (a_v[i] ? ((size_t)(rowBase + p) * KD + a_c4[i] * 4) : 0);
    }
    int b_r[2], b_c4[2];
    #pragma unroll
    for (int i = 0; i < 2; i++) {
        int idx = tid + i * 256;
        b_r[i] = idx >> 3; b_c4[i] = idx & 7;
    }
    auto issue_stage = [&](int c) {
        int buf = c % 3;
        uint32_t aB = sbuf + buf * F2_STAGE;
        uint32_t bB = aB + F_A_BYTES;
        int k0 = c * 32;
        #pragma unroll
        for (int i = 0; i < 4; i++)
            cp_async16(aB + (a_r[i] * ASTR + a_c4[i] * 4) * 4, a_src[i] + k0, a_v[i] ? 16u : 0u);
        #pragma unroll
        for (int i = 0; i < 2; i++) {
            int n = n0 + b_r[i];
            bool bv = (n < NI);
            size_t off = bv ? ((size_t)n * KD + k0 + b_c4[i] * 4) : 0;
            cp_async16(bB + (b_r[i] * ASTR + b_c4[i] * 4) * 4, wp + off, bv ? 16u : 0u);
        }
        CP_COMMIT();
    };
    int lane = tid & 31, grp = lane >> 2, tig = lane & 3;
    int mbase = (wid & 3) * 32, nbase = (wid >> 2) * 32;
    float acc[2][4][4];
    #pragma unroll
    for (int mt = 0; mt < 2; mt++)
        #pragma unroll
        for (int nt = 0; nt < 4; nt++)
            #pragma unroll
            for (int q = 0; q < 4; q++) acc[mt][nt][q] = 0.f;
    issue_stage(0); issue_stage(1);
    for (int c = 0; c < NCHUNK; c++) {
        CP_WAIT1();
        __syncthreads();
        if (c + 2 < NCHUNK) issue_stage(c + 2);
        else CP_COMMIT();
        int buf = c % 3;
        const float* As = (const float*)(smem + 1024 + buf * F2_STAGE);
        const float* Bs = As + 128 * ASTR;
        #pragma unroll
        for (int ks = 0; ks < 4; ks++) {
            int kk = ks * 8;
            uint32_t a[2][4];
            #pragma unroll
            for (int mt = 0; mt < 2; mt++) {
                int r0 = mbase + mt * 16 + grp;
                a[mt][0] = f2tf32(As[r0 * ASTR + kk + tig]);
                a[mt][1] = f2tf32(As[(r0 + 8) * ASTR + kk + tig]);
                a[mt][2] = f2tf32(As[r0 * ASTR + kk + tig + 4]);
                a[mt][3] = f2tf32(As[(r0 + 8) * ASTR + kk + tig + 4]);
            }
            #pragma unroll
            for (int nt = 0; nt < 4; nt++) {
                int cr = nbase + nt * 8 + grp;
                uint32_t b[2];
                b[0] = f2tf32(Bs[cr * ASTR + kk + tig]);
                b[1] = f2tf32(Bs[cr * ASTR + kk + tig + 4]);
                #pragma unroll
                for (int mt = 0; mt < 2; mt++)
                    MMA_TF32_SYNC(acc[mt][nt], a[mt], b);
            }
        }
        __syncthreads();
    }
    #pragma unroll
    for (int mt = 0; mt < 2; mt++) {
        int pr = mbase + mt * 16 + grp;
        #pragma unroll
        for (int nt = 0; nt < 4; nt++) {
            int col = n0 + nbase + nt * 8 + 2 * tig;
            int p = m0 + pr;
            if (p < cnt) {
                float* orow = g_O + (size_t)(rowBase + p) * KD + 1;
                float add = 0.f;
                if (col < NI)     { orow[col]     = acc[mt][nt][0]; add += acc[mt][nt][0]*acc[mt][nt][0]; }
                if (col + 1 < NI) { orow[col + 1] = acc[mt][nt][1]; add += acc[mt][nt][1]*acc[mt][nt][1]; }
                atomicAdd(&s_ps[pr], add);
            }
            int p2 = p + 8;
            if (p2 < cnt) {
                float* orow = g_O + (size_t)(rowBase + p2) * KD + 1;
                float add = 0.f;
                if (col < NI)     { orow[col]     = acc[mt][nt][2]; add += acc[mt][nt][2]*acc[mt][nt][2]; }
                if (col + 1 < NI) { orow[col + 1] = acc[mt][nt][3]; add += acc[mt][nt][3]*acc[mt][nt][3]; }
                atomicAdd(&s_ps[pr + 8], add);
            }
        }
    }
    __syncthreads();
    if (tid < 128) {
        int p = m0 + tid;
        if (p < cnt) g_part2[(size_t)(rowBase + p) * 16 + (n0 >> 6)] = s_ps[tid];
    }
#endif
}

// ------------------------------- launcher --------------------------------------
extern "C" void kernel_launch(void* const* d_in, const int* in_sizes, int n_in,
                              void* d_out, int out_size) {
    const float* x      = (const float*)d_in[0];
    const float* gate_w = (const float*)d_in[1];
    const float* gate_b = (const float*)d_in[2];
    const float* W1     = (const float*)d_in[3];
    const float* W3     = (const float*)d_in[4];
    const float* W2     = (const float*)d_in[5];
    const float* Ws1    = (const float*)d_in[6];
    const float* Ws3    = (const float*)d_in[7];
    const float* Ws2    = (const float*)d_in[8];
    float* out = (float*)d_out;

    cudaFuncSetAttribute(gemm1_tc, cudaFuncAttributeMaxDynamicSharedMemorySize, SMEM1_TOTAL);
    cudaFuncSetAttribute(gemm2_tc, cudaFuncAttributeMaxDynamicSharedMemorySize, SMEM2_TOTAL);

    zero_cnt_kernel<<<1, 32>>>();
    gate_kernel<<<TT / 8, 256>>>(x, gate_w, gate_b);
    dummy_kernel<<<1, 32>>>();
    gemm1_tc<<<dim3(16, 16, 9), 256, SMEM1_TOTAL>>>(x, W1, W3, Ws1, Ws3);  // ncu #6
    norm_kernel<<<16, 256>>>(0);
    gemm2_tc<<<dim3(16, 16, 9), 256, SMEM2_TOTAL>>>(W2, Ws2);
    norm_kernel<<<16, 256>>>(1);
    combine_kernel<<<TT / 8, 256>>>(out);
}

// round 15
// speedup vs baseline: 1.0393x; 1.0393x over previous
#include <cuda_runtime.h>
#include <math.h>
#include <stdint.h>

#define TT 2048
#define DD 1024
#define EE 8
#define NI 1023
#define KD 1024

#define ROWS_ROUTED (EE * TT)
#define SHARED_BASE ROWS_ROUTED
#define TOTAL_ROWS  (ROWS_ROUTED + TT)

#if defined(__CUDA_ARCH_FEAT_SM103_ALL) || defined(__CUDA_ARCH_FEAT_SM100_ALL) || defined(__CUDA_ARCH_FEAT_SM101_ALL)
#define HAS_TCGEN05 1
#else
#define HAS_TCGEN05 0
#endif

// ------------------- device scratch -------------------
__device__ float g_H[(size_t)TOTAL_ROWS * KD];
__device__ float g_O[(size_t)TOTAL_ROWS * KD];
__device__ float g_part1[(size_t)TOTAL_ROWS * 16];   // per-(row, 64-col slot) partials of sp^2
__device__ float g_part2[(size_t)TOTAL_ROWS * 16];   // same for o^2
__device__ int   g_cnt[EE];
__device__ int   g_bucket[ROWS_ROUTED];
__device__ int   g_rowOf[TT];
__device__ float g_wgt[TT];

// ------------------------------ helpers -----------------------------------------
__device__ __forceinline__ uint32_t smem_to_u32(const void* p) {
    uint32_t a;
    asm("{ .reg .u64 t; cvta.to.shared.u64 t, %1; cvt.u32.u64 %0, t; }" : "=r"(a) : "l"(p));
    return a;
}
__device__ __forceinline__ uint32_t f2tf32(float f) {
    uint32_t o; asm("cvt.rna.tf32.f32 %0, %1;" : "=r"(o) : "f"(f)); return o;
}
__device__ __forceinline__ float silu_mul(float v1, float v3) {
    return v1 * v3 / (1.0f + __expf(-v1));
}
__device__ __forceinline__ void cp_async16(uint32_t smem_addr, const void* gptr, uint32_t src_size) {
    asm volatile("cp.async.cg.shared.global [%0], [%1], 16, %2;"
                 :: "r"(smem_addr), "l"(gptr), "r"(src_size) : "memory");
}
#define CP_COMMIT() asm volatile("cp.async.commit_group;" ::: "memory")
#define CP_WAIT1()  asm volatile("cp.async.wait_group 1;" ::: "memory")
#define CP_WAIT2()  asm volatile("cp.async.wait_group 2;" ::: "memory")

#define MBARRIER_INIT(mbar, count) \
    asm volatile("mbarrier.init.shared.b64 [%0], %1;" \
        :: "r"((uint32_t)(mbar)), "r"((uint32_t)(count)) : "memory")
#define MBARRIER_WAIT_PARITY(mbar_smem_addr, phase_parity) do { \
    uint32_t _mbar = (uint32_t)(mbar_smem_addr); \
    uint32_t _parity = (uint32_t)(phase_parity); \
    uint32_t _done; \
    asm volatile("{\n\t.reg .pred p;\n\t" \
        "mbarrier.try_wait.parity.acquire.cta.shared::cta.b64 p, [%1], %2;\n\t" \
        "selp.b32 %0, 1, 0, p;\n\t}" : "=r"(_done) : "r"(_mbar), "r"(_parity) : "memory"); \
    if (!_done) { \
        asm volatile("{\n\t.reg .pred P1;\n\t" \
            "WAIT_LOOP_%=:\n\t" \
            "mbarrier.try_wait.parity.acquire.cta.shared::cta.b64 P1, [%0], %1, 0x989680;\n\t" \
            "@P1 bra.uni WAIT_DONE_%=;\n\t" \
            "bra.uni WAIT_LOOP_%=;\n\t" \
            "WAIT_DONE_%=:\n\t}" :: "r"(_mbar), "r"(_parity) : "memory"); \
    } \
} while(0)

#if HAS_TCGEN05
__device__ __forceinline__ uint32_t elect_one_pred() {
    uint32_t pred;
    asm volatile("{\n\t.reg .pred p;\n\telect.sync _|p, 0xFFFFFFFF;\n\t"
                 "selp.b32 %0, 1, 0, p;\n\t}" : "=r"(pred));
    return pred;
}
#define TCGEN05_ALLOC(smem_result_addr, nCols) \
    asm volatile("tcgen05.alloc.cta_group::1.sync.aligned.shared::cta.b32 [%0], %1;" \
        :: "r"((uint32_t)(smem_result_addr)), "r"((uint32_t)(nCols)) : "memory")
#define TCGEN05_DEALLOC(tmem_addr, nCols) \
    asm volatile("tcgen05.dealloc.cta_group::1.sync.aligned.b32 %0, %1;" \
        :: "r"(tmem_addr), "r"((uint32_t)(nCols)))
#define TCGEN05_COMMIT(mbar_smem_addr) \
    asm volatile("tcgen05.commit.cta_group::1.mbarrier::arrive::one.shared::cluster.b64 [%0];" \
        :: "r"((uint32_t)(mbar_smem_addr)) : "memory")
#define TCGEN05_WAIT_LD() asm volatile("tcgen05.wait::ld.sync.aligned;" ::: "memory")
#define TCGEN05_FENCE_AFTER() asm volatile("tcgen05.fence::after_thread_sync;" ::: "memory")
#define FENCE_PROXY_ASYNC_SHARED_CTA() asm volatile("fence.proxy.async.shared::cta;" ::: "memory")
#define TCGEN05_LD_32X32B_X32(r, tmem_addr) \
    asm volatile("tcgen05.ld.sync.aligned.32x32b.x32.b32 " \
        "{%0, %1, %2, %3, %4, %5, %6, %7, " \
        " %8, %9, %10, %11, %12, %13, %14, %15, " \
        " %16, %17, %18, %19, %20, %21, %22, %23, " \
        " %24, %25, %26, %27, %28, %29, %30, %31}, [%32];" \
        : "=r"((r)[0]),  "=r"((r)[1]),  "=r"((r)[2]),  "=r"((r)[3]), \
          "=r"((r)[4]),  "=r"((r)[5]),  "=r"((r)[6]),  "=r"((r)[7]), \
          "=r"((r)[8]),  "=r"((r)[9]),  "=r"((r)[10]), "=r"((r)[11]), \
          "=r"((r)[12]), "=r"((r)[13]), "=r"((r)[14]), "=r"((r)[15]), \
          "=r"((r)[16]), "=r"((r)[17]), "=r"((r)[18]), "=r"((r)[19]), \
          "=r"((r)[20]), "=r"((r)[21]), "=r"((r)[22]), "=r"((r)[23]), \
          "=r"((r)[24]), "=r"((r)[25]), "=r"((r)[26]), "=r"((r)[27]), \
          "=r"((r)[28]), "=r"((r)[29]), "=r"((r)[30]), "=r"((r)[31]) \
        : "r"(tmem_addr))

static constexpr uint64_t SMEM_DESC_BASE_SW128 =
    (uint64_t(2) << 61) | (uint64_t(1) << 46) | (uint64_t(64) << 32) | (uint64_t(1) << 16);
#define MAKE_SMEM_DESC(base_addr) \
    (SMEM_DESC_BASE_SW128 | ((uint64_t)((base_addr) >> 4) & 0x3FFF))
#define IDESC_TF32_N128 ((1u<<4) | (2u<<7) | (2u<<10) | (16u<<17) | (8u<<24))

__device__ __forceinline__ void mma_tf32_ss(uint32_t d_tmem, uint64_t a_desc,
                                            uint64_t b_desc, uint32_t idesc, bool acc) {
    uint32_t en = acc ? 1u : 0u;
    asm volatile(
        "{\n\t.reg .pred p;\n\tsetp.ne.u32 p, %5, 0;\n\t"
        "tcgen05.mma.cta_group::1.kind::tf32 [%0], %1, %2, %3, {%4, %4, %4, %4}, p;\n\t}"
        :: "r"(d_tmem), "l"(a_desc), "l"(b_desc), "r"(idesc), "r"(0u), "r"(en)
        : "memory");
}
#endif // HAS_TCGEN05

#define MMA_TF32_SYNC(d, a, b) \
    asm volatile("mma.sync.aligned.m16n8k8.row.col.f32.tf32.tf32.f32 " \
        "{%0,%1,%2,%3}, {%4,%5,%6,%7}, {%8,%9}, {%0,%1,%2,%3};" \
        : "+f"((d)[0]), "+f"((d)[1]), "+f"((d)[2]), "+f"((d)[3]) \
        : "r"((a)[0]), "r"((a)[1]), "r"((a)[2]), "r"((a)[3]), \
          "r"((b)[0]), "r"((b)[1]))

// ------------------------------- small kernels ----------------------------------
__device__ __forceinline__ float warp_reduce_sum(float v) {
    #pragma unroll
    for (int o = 16; o; o >>= 1) v += __shfl_xor_sync(0xffffffffu, v, o);
    return v;
}

__global__ void zero_cnt_kernel() {
    if (threadIdx.x < EE) g_cnt[threadIdx.x] = 0;
}

__global__ void gate_kernel(const float* __restrict__ x,
                            const float* __restrict__ gate_w,
                            const float* __restrict__ gate_b) {
    int tid = threadIdx.x;
    int w = tid >> 5, lane = tid & 31;
    __shared__ float sl[8][8];

    float gw_reg[32];
    const float* gr = gate_w + (size_t)w * NI;
    #pragma unroll
    for (int i = 0; i < 32; i++) {
        int c = lane + 32 * i;
        gw_reg[i] = (c < NI) ? gr[c] : 0.0f;
    }
    #pragma unroll
    for (int j = 0; j < 8; j++) {
        int t = blockIdx.x * 8 + j;
        const float* xr = x + (size_t)t * DD + 1;
        float s = 0.0f;
        #pragma unroll
        for (int i = 0; i < 32; i++) {
            int c = lane + 32 * i;
            if (c < NI) s += gw_reg[i] * xr[c];
        }
        s = warp_reduce_sum(s);
        if (lane == 0) sl[j][w] = s;
    }
    __syncthreads();
    if (tid < 8) {
        int t = blockIdx.x * 8 + tid;
        float m = sl[tid][0];
        #pragma unroll
        for (int e = 1; e < EE; e++) m = fmaxf(m, sl[tid][e]);
        float ex[EE], den = 0.0f;
        #pragma unroll
        for (int e = 0; e < EE; e++) { ex[e] = expf(sl[tid][e] - m); den += ex[e]; }
        float inv = 1.0f / den;
        float best = -1e30f; int bi = 0;
        #pragma unroll
        for (int e = 0; e < EE; e++) {
            float biased = ex[e] * inv + gate_b[e];
            if (biased > best) { best = biased; bi = e; }
        }
        g_wgt[t] = ex[bi] * inv;
        int p = atomicAdd(&g_cnt[bi], 1);
        g_bucket[bi * TT + p] = t;
        g_rowOf[t] = bi * TT + p;
    }
}

// combine: er[0], zr[0] computed inline from g_part2 partials (no norm kernel).
__global__ void combine_kernel(float* __restrict__ out) {
    int lane = threadIdx.x & 31;
    int t = blockIdx.x * 8 + (threadIdx.x >> 5);
    int rr = g_rowOf[t];
    int zrow = SHARED_BASE + t;
    float wgt = g_wgt[t];
    const float* zr = g_O + (size_t)zrow * KD;
    const float* er = g_O + (size_t)rr * KD;

    // lanes 0..15 sum part2[rr], lanes 16..31 sum part2[zrow] (segmented reduce)
    float v = (lane < 16) ? g_part2[(size_t)rr * 16 + lane]
                          : g_part2[(size_t)zrow * 16 + (lane - 16)];
    #pragma unroll
    for (int o = 8; o; o >>= 1) v += __shfl_xor_sync(0xffffffffu, v, o);
    float er0 = sqrtf(1.0f + __shfl_sync(0xffffffffu, v, 0));
    float zr0 = sqrtf(1.0f + __shfl_sync(0xffffffffu, v, 16));

    float c0 = zr0 + 2.0f * (1.0f + wgt * er0);     // comb time coord
    float comb[32];
    float ss = 0.0f;
    #pragma unroll
    for (int i = 0; i < 32; i++) {
        int d = lane + 32 * i;
        if (d == 0) {
            comb[i] = c0;
        } else {
            float cv = zr[d] + 2.0f * wgt * er[d];
            comb[i] = cv;
            ss += cv * cv;
        }
    }
    ss = warp_reduce_sum(ss);
    float li = ss - c0 * c0;
    float scale = rsqrtf(fmaxf(fabsf(li), 1e-8f));
    #pragma unroll
    for (int i = 0; i < 32; i++)
        out[(size_t)t * DD + lane + 32 * i] = comb[i] * scale;
}

// ------------------------------ smem layout (round-11 shape) ----------------------
#define SM_TOKS  0
#define SM_MBAR  512
#define SM_TMEMP 528
#define SM_BUF   1024
#define TILE16K  16384
#define T1_STAGE (3 * TILE16K)
#define T2_STAGE (2 * TILE16K)
#define STAGES   4
#define SMEM1_TOTAL (SM_BUF + STAGES * T1_STAGE)   // 197632
#define SMEM2_TOTAL (SM_BUF + STAGES * T2_STAGE)   // 132096
#define NCHUNK 32

// fallback layout constants (non-'a' pass only)
#define ASTR   36
#define F_A_BYTES (128 * ASTR * 4)
#define F_B_BYTES (64  * ASTR * 4)
#define F1_STAGE (F_A_BYTES + 2 * F_B_BYTES)
#define F2_STAGE (F_A_BYTES + F_B_BYTES)

// ------------------------------ GEMM 1 ------------------------------------------
__global__ void __launch_bounds__(256) gemm1_tc(
    const float* __restrict__ x,
    const float* __restrict__ W1, const float* __restrict__ W3,
    const float* __restrict__ Ws1, const float* __restrict__ Ws3)
{
    extern __shared__ char smem[];
    int tid = threadIdx.x;
    int wid = tid >> 5;

    int e = blockIdx.z;
    int cnt; const float *w1p, *w3p; int rowBase;
    if (e < EE) {
        cnt = g_cnt[e];
        w1p = W1 + (size_t)e * NI * KD;
        w3p = W3 + (size_t)e * NI * KD;
        rowBase = e * TT;
    } else {
        cnt = TT; w1p = Ws1; w3p = Ws3; rowBase = SHARED_BASE;
    }
    int m0 = blockIdx.y * 128;
    if (m0 >= cnt) return;

#if HAS_TCGEN05
    if (blockIdx.x & 1) return;
    int n0 = (blockIdx.x >> 1) * 128;
    uint32_t sb = smem_to_u32(smem);

    int* toks = (int*)(smem + SM_TOKS);
    if (tid < 128) {
        int p = m0 + tid;
        toks[tid] = (p < cnt) ? ((e < EE) ? g_bucket[e * TT + p] : p) : -1;
    }
    if (wid == 0) TCGEN05_ALLOC(sb + SM_TMEMP, 256);
    if (tid == 0) { MBARRIER_INIT(sb + SM_MBAR, 1); MBARRIER_INIT(sb + SM_MBAR + 8, 1); }
    __syncthreads();
    uint32_t tmem;
    asm volatile("ld.shared.b32 %0, [%1];" : "=r"(tmem) : "r"(sb + SM_TMEMP));

    uint32_t l_sw[4];
    const float* a_gp[4]; uint32_t a_sz[4];
    const float* b1_gp[4]; const float* b3_gp[4]; uint32_t b_sz[4];
    #pragma unroll
    for (int i = 0; i < 4; i++) {
        int idx = tid + i * 256;
        int r = idx >> 3, c4 = idx & 7;
        uint32_t off = (uint32_t)(r * 128 + c4 * 16);
        l_sw[i] = off ^ ((off >> 3) & 0x70);
        int tok = toks[r];
        a_sz[i] = (tok >= 0) ? 16u : 0u;
        a_gp[i] = x + ((tok >= 0) ? ((size_t)tok * DD + c4 * 4) : 0);
        int n = n0 + r;
        b_sz[i] = (n < NI) ? 16u : 0u;
        size_t boff = (n < NI) ? ((size_t)n * KD + c4 * 4) : 0;
        b1_gp[i] = w1p + boff;
        b3_gp[i] = w3p + boff;
    }

    auto issue_stage = [&](int c) {
        uint32_t base = sb + SM_BUF + (c & 3) * T1_STAGE;
        int k0 = c * 32;
        #pragma unroll
        for (int i = 0; i < 4; i++) {
            cp_async16(base + l_sw[i],                a_gp[i] + k0, a_sz[i]);
            cp_async16(base + TILE16K + l_sw[i],      b1_gp[i] + k0, b_sz[i]);
            cp_async16(base + 2 * TILE16K + l_sw[i],  b3_gp[i] + k0, b_sz[i]);
        }
        CP_COMMIT();
    };

    issue_stage(0); issue_stage(1); issue_stage(2);

    for (int c = 0; c < NCHUNK; c++) {
        CP_WAIT2();
        __syncthreads();
        if (wid == 0) {
            if (elect_one_pred()) {
                FENCE_PROXY_ASYNC_SHARED_CTA();
                uint32_t base = sb + SM_BUF + (c & 3) * T1_STAGE;
                uint64_t ad  = MAKE_SMEM_DESC(base);
                uint64_t b1d = MAKE_SMEM_DESC(base + TILE16K);
                uint64_t b3d = MAKE_SMEM_DESC(base + 2 * TILE16K);
                #pragma unroll
                for (int k = 0; k < 4; k++) {
                    bool acc = (c > 0) || (k > 0);
                    mma_tf32_ss(tmem,       ad + k*2, b1d + k*2, IDESC_TF32_N128, acc);
                    mma_tf32_ss(tmem + 128, ad + k*2, b3d + k*2, IDESC_TF32_N128, acc);
                }
                TCGEN05_COMMIT(sb + SM_MBAR + 8 * (c & 1));
            }
        }
        if (c >= 1)
            MBARRIER_WAIT_PARITY(sb + SM_MBAR + 8 * ((c - 1) & 1), ((c - 1) >> 1) & 1);
        if (c + 3 < NCHUNK) issue_stage(c + 3);
        else CP_COMMIT();
    }
    MBARRIER_WAIT_PARITY(sb + SM_MBAR + 8, 1);   // chunk 31
    __syncthreads();
    TCGEN05_FENCE_AFTER();

    // Epilogue: sp = silu(d1)*d3 with fused row-partials of sp^2
    float* st = (float*)(smem + SM_BUF);
    float psum = 0.0f;
    for (int cb = 0; cb < 128; cb += 32) {
        if (tid < 128) {
            uint32_t d1[32], d2[32];
            TCGEN05_LD_32X32B_X32(d1, tmem + cb);
            TCGEN05_LD_32X32B_X32(d2, tmem + 128 + cb);
            TCGEN05_WAIT_LD();
            #pragma unroll
            for (int j = 0; j < 32; j++) {
                float sp = silu_mul(__uint_as_float(d1[j]), __uint_as_float(d2[j]));
                st[tid * 33 + j] = sp;
                psum += sp * sp;
            }
        }
        __syncthreads();
        #pragma unroll
        for (int i = 0; i < 16; i++) {
            int l = tid + i * 256;
            int r = l >> 5, cc = l & 31;
            int p = m0 + r;
            int col = n0 + cb + cc;
            if (p < cnt && col < NI)
                g_H[(size_t)(rowBase + p) * KD + 1 + col] = st[r * 33 + cc];
        }
        __syncthreads();
    }
    if (tid < 128) {
        int p = m0 + tid;
        if (p < cnt) {
            int slot = n0 >> 6;
            g_part1[(size_t)(rowBase + p) * 16 + slot]     = psum;
            g_part1[(size_t)(rowBase + p) * 16 + slot + 1] = 0.0f;
        }
    }
    if (wid == 0) TCGEN05_DEALLOC(tmem, 256);
#else
    // ---------------- fallback: pipelined mma.sync (compute_103 pass only) --------
    int n0 = blockIdx.x * 64;
    int* toks = (int*)smem;
    uint32_t sbuf = smem_to_u32(smem) + 1024;
    __shared__ float s_ps[128];
    if (tid < 128) {
        int p = m0 + tid;
        toks[tid] = (p < cnt) ? ((e < EE) ? g_bucket[e * TT + p] : p) : -1;
        s_ps[tid] = 0.0f;
    }
    __syncthreads();
    int a_r[4], a_c4[4], a_tok[4];
    #pragma unroll
    for (int i = 0; i < 4; i++) {
        int idx = tid + i * 256;
        a_r[i] = idx >> 3; a_c4[i] = idx & 7; a_tok[i] = toks[a_r[i]];
    }
    int b_r[2], b_c4[2];
    #pragma unroll
    for (int i = 0; i < 2; i++) {
        int idx = tid + i * 256;
        b_r[i] = idx >> 3; b_c4[i] = idx & 7;
    }
    auto issue_stage = [&](int c) {
        int buf = c % 3;
        uint32_t aB  = sbuf + buf * F1_STAGE;
        uint32_t b1B = aB + F_A_BYTES;
        uint32_t b3B = b1B + F_B_BYTES;
        int k0 = c * 32;
        #pragma unroll
        for (int i = 0; i < 4; i++) {
            int tok = a_tok[i];
            const float* src = x + ((tok >= 0) ? ((size_t)tok * DD + k0 + a_c4[i] * 4) : 0);
            cp_async16(aB + (a_r[i] * ASTR + a_c4[i] * 4) * 4, src, (tok >= 0) ? 16u : 0u);
        }
        #pragma unroll
        for (int i = 0; i < 2; i++) {
            int n = n0 + b_r[i];
            bool bv = (n < NI);
            size_t off = bv ? ((size_t)n * KD + k0 + b_c4[i] * 4) : 0;
            uint32_t so = (b_r[i] * ASTR + b_c4[i] * 4) * 4;
            cp_async16(b1B + so, w1p + off, bv ? 16u : 0u);
            cp_async16(b3B + so, w3p + off, bv ? 16u : 0u);
        }
        CP_COMMIT();
    };
    int lane = tid & 31, grp = lane >> 2, tig = lane & 3;
    int mbase = (wid & 3) * 32, nbase = (wid >> 2) * 32;
    float c1[2][4][4], c3[2][4][4];
    #pragma unroll
    for (int mt = 0; mt < 2; mt++)
        #pragma unroll
        for (int nt = 0; nt < 4; nt++)
            #pragma unroll
            for (int q = 0; q < 4; q++) { c1[mt][nt][q] = 0.f; c3[mt][nt][q] = 0.f; }
    issue_stage(0); issue_stage(1);
    for (int c = 0; c < NCHUNK; c++) {
        CP_WAIT1();
        __syncthreads();
        if (c + 2 < NCHUNK) issue_stage(c + 2);
        else CP_COMMIT();
        int buf = c % 3;
        const float* As  = (const float*)(smem + 1024 + buf * F1_STAGE);
        const float* B1s = As + 128 * ASTR;
        const float* B3s = B1s + 64 * ASTR;
        #pragma unroll
        for (int ks = 0; ks < 4; ks++) {
            int kk = ks * 8;
            uint32_t a[2][4];
            #pragma unroll
            for (int mt = 0; mt < 2; mt++) {
                int r0 = mbase + mt * 16 + grp;
                a[mt][0] = f2tf32(As[r0 * ASTR + kk + tig]);
                a[mt][1] = f2tf32(As[(r0 + 8) * ASTR + kk + tig]);
                a[mt][2] = f2tf32(As[r0 * ASTR + kk + tig + 4]);
                a[mt][3] = f2tf32(As[(r0 + 8) * ASTR + kk + tig + 4]);
            }
            uint32_t b1[4][2], b3[4][2];
            #pragma unroll
            for (int nt = 0; nt < 4; nt++) {
                int cr = nbase + nt * 8 + grp;
                b1[nt][0] = f2tf32(B1s[cr * ASTR + kk + tig]);
                b1[nt][1] = f2tf32(B1s[cr * ASTR + kk + tig + 4]);
                b3[nt][0] = f2tf32(B3s[cr * ASTR + kk + tig]);
                b3[nt][1] = f2tf32(B3s[cr * ASTR + kk + tig + 4]);
            }
            #pragma unroll
            for (int mt = 0; mt < 2; mt++)
                #pragma unroll
                for (int nt = 0; nt < 4; nt++) {
                    MMA_TF32_SYNC(c1[mt][nt], a[mt], b1[nt]);
                    MMA_TF32_SYNC(c3[mt][nt], a[mt], b3[nt]);
                }
        }
        __syncthreads();
    }
    #pragma unroll
    for (int mt = 0; mt < 2; mt++) {
        int pr = mbase + mt * 16 + grp;
        #pragma unroll
        for (int nt = 0; nt < 4; nt++) {
            int col = n0 + nbase + nt * 8 + 2 * tig;
            int p = m0 + pr;
            if (p < cnt) {
                float* hrow = g_H + (size_t)(rowBase + p) * KD + 1;
                float s0 = silu_mul(c1[mt][nt][0], c3[mt][nt][0]);
                float s1 = silu_mul(c1[mt][nt][1], c3[mt][nt][1]);
                float add = 0.f;
                if (col < NI)     { hrow[col]     = s0; add += s0 * s0; }
                if (col + 1 < NI) { hrow[col + 1] = s1; add += s1 * s1; }
                atomicAdd(&s_ps[pr], add);
            }
            int p2 = p + 8;
            if (p2 < cnt) {
                float* hrow = g_H + (size_t)(rowBase + p2) * KD + 1;
                float s2 = silu_mul(c1[mt][nt][2], c3[mt][nt][2]);
                float s3 = silu_mul(c1[mt][nt][3], c3[mt][nt][3]);
                float add = 0.f;
                if (col < NI)     { hrow[col]     = s2; add += s2 * s2; }
                if (col + 1 < NI) { hrow[col + 1] = s3; add += s3 * s3; }
                atomicAdd(&s_ps[pr + 8], add);
            }
        }
    }
    __syncthreads();
    if (tid < 128) {
        int p = m0 + tid;
        if (p < cnt) g_part1[(size_t)(rowBase + p) * 16 + (n0 >> 6)] = s_ps[tid];
    }
#endif
}

// ------------------------------ GEMM 2 ------------------------------------------
__global__ void __launch_bounds__(256) gemm2_tc(
    const float* __restrict__ W2, const float* __restrict__ Ws2)
{
    extern __shared__ char smem[];
    int tid = threadIdx.x;
    int wid = tid >> 5;

    int e = blockIdx.z;
    int cnt; const float* wp; int rowBase;
    if (e < EE) { cnt = g_cnt[e]; wp = W2 + (size_t)e * NI * KD; rowBase = e * TT; }
    else        { cnt = TT;       wp = Ws2;                      rowBase = SHARED_BASE; }
    int m0 = blockIdx.y * 128;
    if (m0 >= cnt) return;

#if HAS_TCGEN05
    if (blockIdx.x & 1) return;
    int n0 = (blockIdx.x >> 1) * 128;
    uint32_t sb = smem_to_u32(smem);

    if (wid == 0) TCGEN05_ALLOC(sb + SM_TMEMP, 128);
    if (tid == 0) { MBARRIER_INIT(sb + SM_MBAR, 1); MBARRIER_INIT(sb + SM_MBAR + 8, 1); }
    __syncthreads();
    uint32_t tmem;
    asm volatile("ld.shared.b32 %0, [%1];" : "=r"(tmem) : "r"(sb + SM_TMEMP));

    uint32_t l_sw[4];
    const float* a_gp[4]; uint32_t a_sz[4];
    const float* b_gp[4]; uint32_t b_sz[4];
    #pragma unroll
    for (int i = 0; i < 4; i++) {
        int idx = tid + i * 256;
        int r = idx >> 3, c4 = idx & 7;
        uint32_t off = (uint32_t)(r * 128 + c4 * 16);
        l_sw[i] = off ^ ((off >> 3) & 0x70);
        int p = m0 + r;
        a_sz[i] = (p < cnt) ? 16u : 0u;
        a_gp[i] = g_H + ((p < cnt) ? ((size_t)(rowBase + p) * KD + c4 * 4) : 0);
        int n = n0 + r;
        b_sz[i] = (n < NI) ? 16u : 0u;
        b_gp[i] = wp + ((n < NI) ? ((size_t)n * KD + c4 * 4) : 0);
    }

    auto issue_stage = [&](int c) {
        uint32_t base = sb + SM_BUF + (c & 3) * T2_STAGE;
        int k0 = c * 32;
        #pragma unroll
        for (int i = 0; i < 4; i++) {
            cp_async16(base + l_sw[i],           a_gp[i] + k0, a_sz[i]);
            cp_async16(base + TILE16K + l_sw[i], b_gp[i] + k0, b_sz[i]);
        }
        CP_COMMIT();
    };

    issue_stage(0); issue_stage(1); issue_stage(2);

    for (int c = 0; c < NCHUNK; c++) {
        CP_WAIT2();
        __syncthreads();
        if (c == 0) {
            // Patch A-tile col 0 with the time lift t = sqrt(1 + sum(sp^2)) from g_part1.
            if (tid < 128) {
                int p = m0 + tid;
                if (p < cnt) {
                    const float* pp = g_part1 + (size_t)(rowBase + p) * 16;
                    float s = 1.0f;
                    #pragma unroll
                    for (int j = 0; j < 16; j++) s += pp[j];
                    uint32_t off = (uint32_t)(tid * 128);
                    uint32_t sw = off ^ ((off >> 3) & 0x70);
                    *(float*)(smem + SM_BUF + sw) = sqrtf(s);   // buffer 0, A tile, row tid, col 0
                }
            }
            __syncthreads();
        }
        if (wid == 0) {
            if (elect_one_pred()) {
                FENCE_PROXY_ASYNC_SHARED_CTA();
                uint32_t base = sb + SM_BUF + (c & 3) * T2_STAGE;
                uint64_t ad = MAKE_SMEM_DESC(base);
                uint64_t bd = MAKE_SMEM_DESC(base + TILE16K);
                #pragma unroll
                for (int k = 0; k < 4; k++) {
                    bool acc = (c > 0) || (k > 0);
                    mma_tf32_ss(tmem, ad + k*2, bd + k*2, IDESC_TF32_N128, acc);
                }
                TCGEN05_COMMIT(sb + SM_MBAR + 8 * (c & 1));
            }
        }
        if (c >= 1)
            MBARRIER_WAIT_PARITY(sb + SM_MBAR + 8 * ((c - 1) & 1), ((c - 1) >> 1) & 1);
        if (c + 3 < NCHUNK) issue_stage(c + 3);
        else CP_COMMIT();
    }
    MBARRIER_WAIT_PARITY(sb + SM_MBAR + 8, 1);   // chunk 31
    __syncthreads();
    TCGEN05_FENCE_AFTER();

    float* st = (float*)(smem + SM_BUF);
    float psum = 0.0f;
    for (int cb = 0; cb < 128; cb += 32) {
        if (tid < 128) {
            uint32_t d[32];
            TCGEN05_LD_32X32B_X32(d, tmem + cb);
            TCGEN05_WAIT_LD();
            #pragma unroll
            for (int j = 0; j < 32; j++) {
                float v = __uint_as_float(d[j]);
                st[tid * 33 + j] = v;
                psum += v * v;
            }
        }
        __syncthreads();
        #pragma unroll
        for (int i = 0; i < 16; i++) {
            int l = tid + i * 256;
            int r = l >> 5, cc = l & 31;
            int p = m0 + r;
            int col = n0 + cb + cc;
            if (p < cnt && col < NI)
                g_O[(size_t)(rowBase + p) * KD + 1 + col] = st[r * 33 + cc];
        }
        __syncthreads();
    }
    if (tid < 128) {
        int p = m0 + tid;
        if (p < cnt) {
            int slot = n0 >> 6;
            g_part2[(size_t)(rowBase + p) * 16 + slot]     = psum;
            g_part2[(size_t)(rowBase + p) * 16 + slot + 1] = 0.0f;
        }
    }
    if (wid == 0) TCGEN05_DEALLOC(tmem, 128);
#else
    int n0 = blockIdx.x * 64;
    uint32_t sbuf = smem_to_u32(smem) + 1024;
    __shared__ float s_ps[128];
    if (tid < 128) s_ps[tid] = 0.0f;
    __syncthreads();
    int a_r[4], a_c4[4];
    bool a_v[4];
    const float* a_src[4];
    #pragma unroll
    for (int i = 0; i < 4; i++) {
        int idx = tid + i * 256;
        a_r[i] = idx >> 3; a_c4[i] = idx & 7;
        int p = m0 + a_r[i];
        a_v[i] = (p < cnt);
        a_src[i] = g_H + (a_v[i] ? ((size_t)(rowBase + p) * KD + a_c4[i] * 4) : 0);
    }
    int b_r[2], b_c4[2];
    #pragma unroll
    for (int i = 0; i < 2; i++) {
        int idx = tid + i * 256;
        b_r[i] = idx >> 3; b_c4[i] = idx & 7;
    }
    auto issue_stage = [&](int c) {
        int buf = c % 3;
        uint32_t aB = sbuf + buf * F2_STAGE;
        uint32_t bB = aB + F_A_BYTES;
        int k0 = c * 32;
        #pragma unroll
        for (int i = 0; i < 4; i++)
            cp_async16(aB + (a_r[i] * ASTR + a_c4[i] * 4) * 4, a_src[i] + k0, a_v[i] ? 16u : 0u);
        #pragma unroll
        for (int i = 0; i < 2; i++) {
            int n = n0 + b_r[i];
            bool bv = (n < NI);
            size_t off = bv ? ((size_t)n * KD + k0 + b_c4[i] * 4) : 0;
            cp_async16(bB + (b_r[i] * ASTR + b_c4[i] * 4) * 4, wp + off, bv ? 16u : 0u);
        }
        CP_COMMIT();
    };
    int lane = tid & 31, grp = lane >> 2, tig = lane & 3;
    int mbase = (wid & 3) * 32, nbase = (wid >> 2) * 32;
    float acc[2][4][4];
    #pragma unroll
    for (int mt = 0; mt < 2; mt++)
        #pragma unroll
        for (int nt = 0; nt < 4; nt++)
            #pragma unroll
            for (int q = 0; q < 4; q++) acc[mt][nt][q] = 0.f;
    issue_stage(0); issue_stage(1);
    for (int c = 0; c < NCHUNK; c++) {
        CP_WAIT1();
        __syncthreads();
        if (c == 0) {
            if (tid < 128) {
                int p = m0 + tid;
                if (p < cnt) {
                    const float* pp = g_part1 + (size_t)(rowBase + p) * 16;
                    float s = 1.0f;
                    #pragma unroll
                    for (int j = 0; j < 16; j++) s += pp[j];
                    ((float*)(smem + 1024))[tid * ASTR] = sqrtf(s);   // buffer 0, A row tid, col 0
                }
            }
            __syncthreads();
        }
        if (c + 2 < NCHUNK) issue_stage(c + 2);
        else CP_COMMIT();
        int buf = c % 3;
        const float* As = (const float*)(smem + 1024 + buf * F2_STAGE);
        const float* Bs = As + 128 * ASTR;
        #pragma unroll
        for (int ks = 0; ks < 4; ks++) {
            int kk = ks * 8;
            uint32_t a[2][4];
            #pragma unroll
            for (int mt = 0; mt < 2; mt++) {
                int r0 = mbase + mt * 16 + grp;
                a[mt][0] = f2tf32(As[r0 * ASTR + kk + tig]);
                a[mt][1] = f2tf32(As[(r0 + 8) * ASTR + kk + tig]);
                a[mt][2] = f2tf32(As[r0 * ASTR + kk + tig + 4]);
                a[mt][3] = f2tf32(As[(r0 + 8) * ASTR + kk + tig + 4]);
            }
            #pragma unroll
            for (int nt = 0; nt < 4; nt++) {
                int cr = nbase + nt * 8 + grp;
                uint32_t b[2];
                b[0] = f2tf32(Bs[cr * ASTR + kk + tig]);
                b[1] = f2tf32(Bs[cr * ASTR + kk + tig + 4]);
                #pragma unroll
                for (int mt = 0; mt < 2; mt++)
                    MMA_TF32_SYNC(acc[mt][nt], a[mt], b);
            }
        }
        __syncthreads();
    }
    #pragma unroll
    for (int mt = 0; mt < 2; mt++) {
        int pr = mbase + mt * 16 + grp;
        #pragma unroll
        for (int nt = 0; nt < 4; nt++) {
            int col = n0 + nbase + nt * 8 + 2 * tig;
            int p = m0 + pr;
            if (p < cnt) {
                float* orow = g_O + (size_t)(rowBase + p) * KD + 1;
                float add = 0.f;
                if (col < NI)     { orow[col]     = acc[mt][nt][0]; add += acc[mt][nt][0]*acc[mt][nt][0]; }
                if (col + 1 < NI) { orow[col + 1] = acc[mt][nt][1]; add += acc[mt][nt][1]*acc[mt][nt][1]; }
                atomicAdd(&s_ps[pr], add);
            }
            int p2 = p + 8;
            if (p2 < cnt) {
                float* orow = g_O + (size_t)(rowBase + p2) * KD + 1;
                float add = 0.f;
                if (col < NI)     { orow[col]     = acc[mt][nt][2]; add += acc[mt][nt][2]*acc[mt][nt][2]; }
                if (col + 1 < NI) { orow[col + 1] = acc[mt][nt][3]; add += acc[mt][nt][3]*acc[mt][nt][3]; }
                atomicAdd(&s_ps[pr + 8], add);
            }
        }
    }
    __syncthreads();
    if (tid < 128) {
        int p = m0 + tid;
        if (p < cnt) g_part2[(size_t)(rowBase + p) * 16 + (n0 >> 6)] = s_ps[tid];
    }
#endif
}

// ------------------------------- launcher --------------------------------------
extern "C" void kernel_launch(void* const* d_in, const int* in_sizes, int n_in,
                              void* d_out, int out_size) {
    const float* x      = (const float*)d_in[0];
    const float* gate_w = (const float*)d_in[1];
    const float* gate_b = (const float*)d_in[2];
    const float* W1     = (const float*)d_in[3];
    const float* W3     = (const float*)d_in[4];
    const float* W2     = (const float*)d_in[5];
    const float* Ws1    = (const float*)d_in[6];
    const float* Ws3    = (const float*)d_in[7];
    const float* Ws2    = (const float*)d_in[8];
    float* out = (float*)d_out;

    cudaFuncSetAttribute(gemm1_tc, cudaFuncAttributeMaxDynamicSharedMemorySize, SMEM1_TOTAL);
    cudaFuncSetAttribute(gemm2_tc, cudaFuncAttributeMaxDynamicSharedMemorySize, SMEM2_TOTAL);

    zero_cnt_kernel<<<1, 32>>>();
    gate_kernel<<<TT / 8, 256>>>(x, gate_w, gate_b);
    gemm1_tc<<<dim3(16, 16, 9), 256, SMEM1_TOTAL>>>(x, W1, W3, Ws1, Ws3);
    gemm2_tc<<<dim3(16, 16, 9), 256, SMEM2_TOTAL>>>(W2, Ws2);
    combine_kernel<<<TT / 8, 256>>>(out);
}

// round 16
// speedup vs baseline: 1.0441x; 1.0046x over previous
#include <cuda_runtime.h>
#include <math.h>
#include <stdint.h>

#define TT 2048
#define DD 1024
#define EE 8
#define NI 1023
#define KD 1024

#define ROWS_ROUTED (EE * TT)
#define SHARED_BASE ROWS_ROUTED
#define TOTAL_ROWS  (ROWS_ROUTED + TT)

#if defined(__CUDA_ARCH_FEAT_SM103_ALL) || defined(__CUDA_ARCH_FEAT_SM100_ALL) || defined(__CUDA_ARCH_FEAT_SM101_ALL)
#define HAS_TCGEN05 1
#else
#define HAS_TCGEN05 0
#endif

// ------------------- device scratch -------------------
__device__ float g_H[(size_t)TOTAL_ROWS * KD];
__device__ float g_O[(size_t)TOTAL_ROWS * KD];
__device__ float g_part1[(size_t)TOTAL_ROWS * 16];   // per-(row, 64-col slot) partials of sp^2
__device__ float g_part2[(size_t)TOTAL_ROWS * 16];   // same for o^2
__device__ int   g_cnt[EE];                          // zero at load; re-zeroed by combine
__device__ int   g_bucket[ROWS_ROUTED];
__device__ int   g_rowOf[TT];
__device__ float g_wgt[TT];

// ------------------------------ helpers -----------------------------------------
__device__ __forceinline__ uint32_t smem_to_u32(const void* p) {
    uint32_t a;
    asm("{ .reg .u64 t; cvta.to.shared.u64 t, %1; cvt.u32.u64 %0, t; }" : "=r"(a) : "l"(p));
    return a;
}
__device__ __forceinline__ uint32_t f2tf32(float f) {
    uint32_t o; asm("cvt.rna.tf32.f32 %0, %1;" : "=r"(o) : "f"(f)); return o;
}
__device__ __forceinline__ float silu_mul(float v1, float v3) {
    return v1 * v3 / (1.0f + __expf(-v1));
}
__device__ __forceinline__ void cp_async16(uint32_t smem_addr, const void* gptr, uint32_t src_size) {
    asm volatile("cp.async.cg.shared.global [%0], [%1], 16, %2;"
                 :: "r"(smem_addr), "l"(gptr), "r"(src_size) : "memory");
}
#define CP_COMMIT() asm volatile("cp.async.commit_group;" ::: "memory")
#define CP_WAIT1()  asm volatile("cp.async.wait_group 1;" ::: "memory")
#define CP_WAIT2()  asm volatile("cp.async.wait_group 2;" ::: "memory")

#define MBARRIER_INIT(mbar, count) \
    asm volatile("mbarrier.init.shared.b64 [%0], %1;" \
        :: "r"((uint32_t)(mbar)), "r"((uint32_t)(count)) : "memory")
#define MBARRIER_WAIT_PARITY(mbar_smem_addr, phase_parity) do { \
    uint32_t _mbar = (uint32_t)(mbar_smem_addr); \
    uint32_t _parity = (uint32_t)(phase_parity); \
    uint32_t _done; \
    asm volatile("{\n\t.reg .pred p;\n\t" \
        "mbarrier.try_wait.parity.acquire.cta.shared::cta.b64 p, [%1], %2;\n\t" \
        "selp.b32 %0, 1, 0, p;\n\t}" : "=r"(_done) : "r"(_mbar), "r"(_parity) : "memory"); \
    if (!_done) { \
        asm volatile("{\n\t.reg .pred P1;\n\t" \
            "WAIT_LOOP_%=:\n\t" \
            "mbarrier.try_wait.parity.acquire.cta.shared::cta.b64 P1, [%0], %1, 0x989680;\n\t" \
            "@P1 bra.uni WAIT_DONE_%=;\n\t" \
            "bra.uni WAIT_LOOP_%=;\n\t" \
            "WAIT_DONE_%=:\n\t}" :: "r"(_mbar), "r"(_parity) : "memory"); \
    } \
} while(0)

#if HAS_TCGEN05
__device__ __forceinline__ uint32_t elect_one_pred() {
    uint32_t pred;
    asm volatile("{\n\t.reg .pred p;\n\telect.sync _|p, 0xFFFFFFFF;\n\t"
                 "selp.b32 %0, 1, 0, p;\n\t}" : "=r"(pred));
    return pred;
}
#define TCGEN05_ALLOC(smem_result_addr, nCols) \
    asm volatile("tcgen05.alloc.cta_group::1.sync.aligned.shared::cta.b32 [%0], %1;" \
        :: "r"((uint32_t)(smem_result_addr)), "r"((uint32_t)(nCols)) : "memory")
#define TCGEN05_DEALLOC(tmem_addr, nCols) \
    asm volatile("tcgen05.dealloc.cta_group::1.sync.aligned.b32 %0, %1;" \
        :: "r"(tmem_addr), "r"((uint32_t)(nCols)))
#define TCGEN05_COMMIT(mbar_smem_addr) \
    asm volatile("tcgen05.commit.cta_group::1.mbarrier::arrive::one.shared::cluster.b64 [%0];" \
        :: "r"((uint32_t)(mbar_smem_addr)) : "memory")
#define TCGEN05_WAIT_LD() asm volatile("tcgen05.wait::ld.sync.aligned;" ::: "memory")
#define TCGEN05_FENCE_AFTER() asm volatile("tcgen05.fence::after_thread_sync;" ::: "memory")
#define FENCE_PROXY_ASYNC_SHARED_CTA() asm volatile("fence.proxy.async.shared::cta;" ::: "memory")
#define TCGEN05_LD_32X32B_X32(r, tmem_addr) \
    asm volatile("tcgen05.ld.sync.aligned.32x32b.x32.b32 " \
        "{%0, %1, %2, %3, %4, %5, %6, %7, " \
        " %8, %9, %10, %11, %12, %13, %14, %15, " \
        " %16, %17, %18, %19, %20, %21, %22, %23, " \
        " %24, %25, %26, %27, %28, %29, %30, %31}, [%32];" \
        : "=r"((r)[0]),  "=r"((r)[1]),  "=r"((r)[2]),  "=r"((r)[3]), \
          "=r"((r)[4]),  "=r"((r)[5]),  "=r"((r)[6]),  "=r"((r)[7]), \
          "=r"((r)[8]),  "=r"((r)[9]),  "=r"((r)[10]), "=r"((r)[11]), \
          "=r"((r)[12]), "=r"((r)[13]), "=r"((r)[14]), "=r"((r)[15]), \
          "=r"((r)[16]), "=r"((r)[17]), "=r"((r)[18]), "=r"((r)[19]), \
          "=r"((r)[20]), "=r"((r)[21]), "=r"((r)[22]), "=r"((r)[23]), \
          "=r"((r)[24]), "=r"((r)[25]), "=r"((r)[26]), "=r"((r)[27]), \
          "=r"((r)[28]), "=r"((r)[29]), "=r"((r)[30]), "=r"((r)[31]) \
        : "r"(tmem_addr))

static constexpr uint64_t SMEM_DESC_BASE_SW128 =
    (uint64_t(2) << 61) | (uint64_t(1) << 46) | (uint64_t(64) << 32) | (uint64_t(1) << 16);
#define MAKE_SMEM_DESC(base_addr) \
    (SMEM_DESC_BASE_SW128 | ((uint64_t)((base_addr) >> 4) & 0x3FFF))
#define IDESC_TF32_N128 ((1u<<4) | (2u<<7) | (2u<<10) | (16u<<17) | (8u<<24))

__device__ __forceinline__ void mma_tf32_ss(uint32_t d_tmem, uint64_t a_desc,
                                            uint64_t b_desc, uint32_t idesc, bool acc) {
    uint32_t en = acc ? 1u : 0u;
    asm volatile(
        "{\n\t.reg .pred p;\n\tsetp.ne.u32 p, %5, 0;\n\t"
        "tcgen05.mma.cta_group::1.kind::tf32 [%0], %1, %2, %3, {%4, %4, %4, %4}, p;\n\t}"
        :: "r"(d_tmem), "l"(a_desc), "l"(b_desc), "r"(idesc), "r"(0u), "r"(en)
        : "memory");
}
#endif // HAS_TCGEN05

#define MMA_TF32_SYNC(d, a, b) \
    asm volatile("mma.sync.aligned.m16n8k8.row.col.f32.tf32.tf32.f32 " \
        "{%0,%1,%2,%3}, {%4,%5,%6,%7}, {%8,%9}, {%0,%1,%2,%3};" \
        : "+f"((d)[0]), "+f"((d)[1]), "+f"((d)[2]), "+f"((d)[3]) \
        : "r"((a)[0]), "r"((a)[1]), "r"((a)[2]), "r"((a)[3]), \
          "r"((b)[0]), "r"((b)[1]))

// ------------------------------- small kernels ----------------------------------
__device__ __forceinline__ float warp_reduce_sum(float v) {
    #pragma unroll
    for (int o = 16; o; o >>= 1) v += __shfl_xor_sync(0xffffffffu, v, o);
    return v;
}

__global__ void gate_kernel(const float* __restrict__ x,
                            const float* __restrict__ gate_w,
                            const float* __restrict__ gate_b) {
    int tid = threadIdx.x;
    int w = tid >> 5, lane = tid & 31;
    __shared__ float sl[8][8];

    float gw_reg[32];
    const float* gr = gate_w + (size_t)w * NI;
    #pragma unroll
    for (int i = 0; i < 32; i++) {
        int c = lane + 32 * i;
        gw_reg[i] = (c < NI) ? gr[c] : 0.0f;
    }
    #pragma unroll
    for (int j = 0; j < 8; j++) {
        int t = blockIdx.x * 8 + j;
        const float* xr = x + (size_t)t * DD + 1;
        float s = 0.0f;
        #pragma unroll
        for (int i = 0; i < 32; i++) {
            int c = lane + 32 * i;
            if (c < NI) s += gw_reg[i] * xr[c];
        }
        s = warp_reduce_sum(s);
        if (lane == 0) sl[j][w] = s;
    }
    __syncthreads();
    if (tid < 8) {
        int t = blockIdx.x * 8 + tid;
        float m = sl[tid][0];
        #pragma unroll
        for (int e = 1; e < EE; e++) m = fmaxf(m, sl[tid][e]);
        float ex[EE], den = 0.0f;
        #pragma unroll
        for (int e = 0; e < EE; e++) { ex[e] = expf(sl[tid][e] - m); den += ex[e]; }
        float inv = 1.0f / den;
        float best = -1e30f; int bi = 0;
        #pragma unroll
        for (int e = 0; e < EE; e++) {
            float biased = ex[e] * inv + gate_b[e];
            if (biased > best) { best = biased; bi = e; }
        }
        g_wgt[t] = ex[bi] * inv;
        int p = atomicAdd(&g_cnt[bi], 1);
        g_bucket[bi * TT + p] = t;
        g_rowOf[t] = bi * TT + p;
    }
}

// combine: er[0], zr[0] computed inline from g_part2 partials; re-zeros g_cnt
// at the end so every graph replay starts with clean counters (no zero kernel).
__global__ void combine_kernel(float* __restrict__ out) {
    int lane = threadIdx.x & 31;
    int t = blockIdx.x * 8 + (threadIdx.x >> 5);
    int rr = g_rowOf[t];
    int zrow = SHARED_BASE + t;
    float wgt = g_wgt[t];
    const float* zr = g_O + (size_t)zrow * KD;
    const float* er = g_O + (size_t)rr * KD;

    float v = (lane < 16) ? g_part2[(size_t)rr * 16 + lane]
                          : g_part2[(size_t)zrow * 16 + (lane - 16)];
    #pragma unroll
    for (int o = 8; o; o >>= 1) v += __shfl_xor_sync(0xffffffffu, v, o);
    float er0 = sqrtf(1.0f + __shfl_sync(0xffffffffu, v, 0));
    float zr0 = sqrtf(1.0f + __shfl_sync(0xffffffffu, v, 16));

    float c0 = zr0 + 2.0f * (1.0f + wgt * er0);
    float comb[32];
    float ss = 0.0f;
    #pragma unroll
    for (int i = 0; i < 32; i++) {
        int d = lane + 32 * i;
        if (d == 0) {
            comb[i] = c0;
        } else {
            float cv = zr[d] + 2.0f * wgt * er[d];
            comb[i] = cv;
            ss += cv * cv;
        }
    }
    ss = warp_reduce_sum(ss);
    float li = ss - c0 * c0;
    float scale = rsqrtf(fmaxf(fabsf(li), 1e-8f));
    #pragma unroll
    for (int i = 0; i < 32; i++)
        out[(size_t)t * DD + lane + 32 * i] = comb[i] * scale;

    // reset routing counters for the next replay (deterministic; g_cnt unused here)
    if (blockIdx.x == 0 && threadIdx.x < EE) g_cnt[threadIdx.x] = 0;
}

// ------------------------------ smem layout (round-11 shape) ----------------------
#define SM_TOKS  0
#define SM_MBAR  512
#define SM_TMEMP 528
#define SM_BUF   1024
#define TILE16K  16384
#define T1_STAGE (3 * TILE16K)
#define T2_STAGE (2 * TILE16K)
#define STAGES   4
#define SMEM1_TOTAL (SM_BUF + STAGES * T1_STAGE)   // 197632
#define SMEM2_TOTAL (SM_BUF + STAGES * T2_STAGE)   // 132096
#define NCHUNK 32

// fallback layout constants (non-'a' pass only)
#define ASTR   36
#define F_A_BYTES (128 * ASTR * 4)
#define F_B_BYTES (64  * ASTR * 4)
#define F1_STAGE (F_A_BYTES + 2 * F_B_BYTES)
#define F2_STAGE (F_A_BYTES + F_B_BYTES)

// ------------------------------ GEMM 1 ------------------------------------------
__global__ void __launch_bounds__(256) gemm1_tc(
    const float* __restrict__ x,
    const float* __restrict__ W1, const float* __restrict__ W3,
    const float* __restrict__ Ws1, const float* __restrict__ Ws3)
{
    extern __shared__ char smem[];
    int tid = threadIdx.x;
    int wid = tid >> 5;

    int e = blockIdx.z;
    int cnt; const float *w1p, *w3p; int rowBase;
    if (e < EE) {
        cnt = g_cnt[e];
        w1p = W1 + (size_t)e * NI * KD;
        w3p = W3 + (size_t)e * NI * KD;
        rowBase = e * TT;
    } else {
        cnt = TT; w1p = Ws1; w3p = Ws3; rowBase = SHARED_BASE;
    }
    int m0 = blockIdx.y * 128;
    if (m0 >= cnt) return;

#if HAS_TCGEN05
    if (blockIdx.x & 1) return;
    int n0 = (blockIdx.x >> 1) * 128;
    uint32_t sb = smem_to_u32(smem);

    int* toks = (int*)(smem + SM_TOKS);
    if (tid < 128) {
        int p = m0 + tid;
        toks[tid] = (p < cnt) ? ((e < EE) ? g_bucket[e * TT + p] : p) : -1;
    }
    if (wid == 0) TCGEN05_ALLOC(sb + SM_TMEMP, 256);
    if (tid == 0) { MBARRIER_INIT(sb + SM_MBAR, 1); MBARRIER_INIT(sb + SM_MBAR + 8, 1); }
    __syncthreads();
    uint32_t tmem;
    asm volatile("ld.shared.b32 %0, [%1];" : "=r"(tmem) : "r"(sb + SM_TMEMP));

    uint32_t l_sw[4];
    const float* a_gp[4]; uint32_t a_sz[4];
    const float* b1_gp[4]; const float* b3_gp[4]; uint32_t b_sz[4];
    #pragma unroll
    for (int i = 0; i < 4; i++) {
        int idx = tid + i * 256;
        int r = idx >> 3, c4 = idx & 7;
        uint32_t off = (uint32_t)(r * 128 + c4 * 16);
        l_sw[i] = off ^ ((off >> 3) & 0x70);
        int tok = toks[r];
        a_sz[i] = (tok >= 0) ? 16u : 0u;
        a_gp[i] = x + ((tok >= 0) ? ((size_t)tok * DD + c4 * 4) : 0);
        int n = n0 + r;
        b_sz[i] = (n < NI) ? 16u : 0u;
        size_t boff = (n < NI) ? ((size_t)n * KD + c4 * 4) : 0;
        b1_gp[i] = w1p + boff;
        b3_gp[i] = w3p + boff;
    }

    auto issue_stage = [&](int c) {
        uint32_t base = sb + SM_BUF + (c & 3) * T1_STAGE;
        int k0 = c * 32;
        #pragma unroll
        for (int i = 0; i < 4; i++) {
            cp_async16(base + l_sw[i],                a_gp[i] + k0, a_sz[i]);
            cp_async16(base + TILE16K + l_sw[i],      b1_gp[i] + k0, b_sz[i]);
            cp_async16(base + 2 * TILE16K + l_sw[i],  b3_gp[i] + k0, b_sz[i]);
        }
        CP_COMMIT();
    };

    issue_stage(0); issue_stage(1); issue_stage(2);

    for (int c = 0; c < NCHUNK; c++) {
        CP_WAIT2();
        __syncthreads();
        if (wid == 0) {
            if (elect_one_pred()) {
                FENCE_PROXY_ASYNC_SHARED_CTA();
                uint32_t base = sb + SM_BUF + (c & 3) * T1_STAGE;
                uint64_t ad  = MAKE_SMEM_DESC(base);
                uint64_t b1d = MAKE_SMEM_DESC(base + TILE16K);
                uint64_t b3d = MAKE_SMEM_DESC(base + 2 * TILE16K);
                #pragma unroll
                for (int k = 0; k < 4; k++) {
                    bool acc = (c > 0) || (k > 0);
                    mma_tf32_ss(tmem,       ad + k*2, b1d + k*2, IDESC_TF32_N128, acc);
                    mma_tf32_ss(tmem + 128, ad + k*2, b3d + k*2, IDESC_TF32_N128, acc);
                }
                TCGEN05_COMMIT(sb + SM_MBAR + 8 * (c & 1));
            }
        }
        if (c >= 1)
            MBARRIER_WAIT_PARITY(sb + SM_MBAR + 8 * ((c - 1) & 1), ((c - 1) >> 1) & 1);
        if (c + 3 < NCHUNK) issue_stage(c + 3);
        else CP_COMMIT();
    }
    MBARRIER_WAIT_PARITY(sb + SM_MBAR + 8, 1);   // chunk 31
    __syncthreads();
    TCGEN05_FENCE_AFTER();

    // Epilogue: sp = silu(d1)*d3 with fused row-partials of sp^2
    float* st = (float*)(smem + SM_BUF);
    float psum = 0.0f;
    for (int cb = 0; cb < 128; cb += 32) {
        if (tid < 128) {
            uint32_t d1[32], d2[32];
            TCGEN05_LD_32X32B_X32(d1, tmem + cb);
            TCGEN05_LD_32X32B_X32(d2, tmem + 128 + cb);
            TCGEN05_WAIT_LD();
            #pragma unroll
            for (int j = 0; j < 32; j++) {
                float sp = silu_mul(__uint_as_float(d1[j]), __uint_as_float(d2[j]));
                st[tid * 33 + j] = sp;
                psum += sp * sp;
            }
        }
        __syncthreads();
        #pragma unroll
        for (int i = 0; i < 16; i++) {
            int l = tid + i * 256;
            int r = l >> 5, cc = l & 31;
            int p = m0 + r;
            int col = n0 + cb + cc;
            if (p < cnt && col < NI)
                g_H[(size_t)(rowBase + p) * KD + 1 + col] = st[r * 33 + cc];
        }
        __syncthreads();
    }
    if (tid < 128) {
        int p = m0 + tid;
        if (p < cnt) {
            int slot = n0 >> 6;
            g_part1[(size_t)(rowBase + p) * 16 + slot]     = psum;
            g_part1[(size_t)(rowBase + p) * 16 + slot + 1] = 0.0f;
        }
    }
    if (wid == 0) TCGEN05_DEALLOC(tmem, 256);
#else
    // ---------------- fallback: pipelined mma.sync (compute_103 pass only) --------
    int n0 = blockIdx.x * 64;
    int* toks = (int*)smem;
    uint32_t sbuf = smem_to_u32(smem) + 1024;
    __shared__ float s_ps[128];
    if (tid < 128) {
        int p = m0 + tid;
        toks[tid] = (p < cnt) ? ((e < EE) ? g_bucket[e * TT + p] : p) : -1;
        s_ps[tid] = 0.0f;
    }
    __syncthreads();
    int a_r[4], a_c4[4], a_tok[4];
    #pragma unroll
    for (int i = 0; i < 4; i++) {
        int idx = tid + i * 256;
        a_r[i] = idx >> 3; a_c4[i] = idx & 7; a_tok[i] = toks[a_r[i]];
    }
    int b_r[2], b_c4[2];
    #pragma unroll
    for (int i = 0; i < 2; i++) {
        int idx = tid + i * 256;
        b_r[i] = idx >> 3; b_c4[i] = idx & 7;
    }
    auto issue_stage = [&](int c) {
        int buf = c % 3;
        uint32_t aB  = sbuf + buf * F1_STAGE;
        uint32_t b1B = aB + F_A_BYTES;
        uint32_t b3B = b1B + F_B_BYTES;
        int k0 = c * 32;
        #pragma unroll
        for (int i = 0; i < 4; i++) {
            int tok = a_tok[i];
            const float* src = x + ((tok >= 0) ? ((size_t)tok * DD + k0 + a_c4[i] * 4) : 0);
            cp_async16(aB + (a_r[i] * ASTR + a_c4[i] * 4) * 4, src, (tok >= 0) ? 16u : 0u);
        }
        #pragma unroll
        for (int i = 0; i < 2; i++) {
            int n = n0 + b_r[i];
            bool bv = (n < NI);
            size_t off = bv ? ((size_t)n * KD + k0 + b_c4[i] * 4) : 0;
            uint32_t so = (b_r[i] * ASTR + b_c4[i] * 4) * 4;
            cp_async16(b1B + so, w1p + off, bv ? 16u : 0u);
            cp_async16(b3B + so, w3p + off, bv ? 16u : 0u);
        }
        CP_COMMIT();
    };
    int lane = tid & 31, grp = lane >> 2, tig = lane & 3;
    int mbase = (wid & 3) * 32, nbase = (wid >> 2) * 32;
    float c1[2][4][4], c3[2][4][4];
    #pragma unroll
    for (int mt = 0; mt < 2; mt++)
        #pragma unroll
        for (int nt = 0; nt < 4; nt++)
            #pragma unroll
            for (int q = 0; q < 4; q++) { c1[mt][nt][q] = 0.f; c3[mt][nt][q] = 0.f; }
    issue_stage(0); issue_stage(1);
    for (int c = 0; c < NCHUNK; c++) {
        CP_WAIT1();
        __syncthreads();
        if (c + 2 < NCHUNK) issue_stage(c + 2);
        else CP_COMMIT();
        int buf = c % 3;
        const float* As  = (const float*)(smem + 1024 + buf * F1_STAGE);
        const float* B1s = As + 128 * ASTR;
        const float* B3s = B1s + 64 * ASTR;
        #pragma unroll
        for (int ks = 0; ks < 4; ks++) {
            int kk = ks * 8;
            uint32_t a[2][4];
            #pragma unroll
            for (int mt = 0; mt < 2; mt++) {
                int r0 = mbase + mt * 16 + grp;
                a[mt][0] = f2tf32(As[r0 * ASTR + kk + tig]);
                a[mt][1] = f2tf32(As[(r0 + 8) * ASTR + kk + tig]);
                a[mt][2] = f2tf32(As[r0 * ASTR + kk + tig + 4]);
                a[mt][3] = f2tf32(As[(r0 + 8) * ASTR + kk + tig + 4]);
            }
            uint32_t b1[4][2], b3[4][2];
            #pragma unroll
            for (int nt = 0; nt < 4; nt++) {
                int cr = nbase + nt * 8 + grp;
                b1[nt][0] = f2tf32(B1s[cr * ASTR + kk + tig]);
                b1[nt][1] = f2tf32(B1s[cr * ASTR + kk + tig + 4]);
                b3[nt][0] = f2tf32(B3s[cr * ASTR + kk + tig]);
                b3[nt][1] = f2tf32(B3s[cr * ASTR + kk + tig + 4]);
            }
            #pragma unroll
            for (int mt = 0; mt < 2; mt++)
                #pragma unroll
                for (int nt = 0; nt < 4; nt++) {
                    MMA_TF32_SYNC(c1[mt][nt], a[mt], b1[nt]);
                    MMA_TF32_SYNC(c3[mt][nt], a[mt], b3[nt]);
                }
        }
        __syncthreads();
    }
    #pragma unroll
    for (int mt = 0; mt < 2; mt++) {
        int pr = mbase + mt * 16 + grp;
        #pragma unroll
        for (int nt = 0; nt < 4; nt++) {
            int col = n0 + nbase + nt * 8 + 2 * tig;
            int p = m0 + pr;
            if (p < cnt) {
                float* hrow = g_H + (size_t)(rowBase + p) * KD + 1;
                float s0 = silu_mul(c1[mt][nt][0], c3[mt][nt][0]);
                float s1 = silu_mul(c1[mt][nt][1], c3[mt][nt][1]);
                float add = 0.f;
                if (col < NI)     { hrow[col]     = s0; add += s0 * s0; }
                if (col + 1 < NI) { hrow[col + 1] = s1; add += s1 * s1; }
                atomicAdd(&s_ps[pr], add);
            }
            int p2 = p + 8;
            if (p2 < cnt) {
                float* hrow = g_H + (size_t)(rowBase + p2) * KD + 1;
                float s2 = silu_mul(c1[mt][nt][2], c3[mt][nt][2]);
                float s3 = silu_mul(c1[mt][nt][3], c3[mt][nt][3]);
                float add = 0.f;
                if (col < NI)     { hrow[col]     = s2; add += s2 * s2; }
                if (col + 1 < NI) { hrow[col + 1] = s3; add += s3 * s3; }
                atomicAdd(&s_ps[pr + 8], add);
            }
        }
    }
    __syncthreads();
    if (tid < 128) {
        int p = m0 + tid;
        if (p < cnt) g_part1[(size_t)(rowBase + p) * 16 + (n0 >> 6)] = s_ps[tid];
    }
#endif
}

// ------------------------------ GEMM 2 ------------------------------------------
__global__ void __launch_bounds__(256) gemm2_tc(
    const float* __restrict__ W2, const float* __restrict__ Ws2)
{
    extern __shared__ char smem[];
    int tid = threadIdx.x;
    int wid = tid >> 5;

    int e = blockIdx.z;
    int cnt; const float* wp; int rowBase;
    if (e < EE) { cnt = g_cnt[e]; wp = W2 + (size_t)e * NI * KD; rowBase = e * TT; }
    else        { cnt = TT;       wp = Ws2;                      rowBase = SHARED_BASE; }
    int m0 = blockIdx.y * 128;
    if (m0 >= cnt) return;

#if HAS_TCGEN05
    if (blockIdx.x & 1) return;
    int n0 = (blockIdx.x >> 1) * 128;
    uint32_t sb = smem_to_u32(smem);

    if (wid == 0) TCGEN05_ALLOC(sb + SM_TMEMP, 128);
    if (tid == 0) { MBARRIER_INIT(sb + SM_MBAR, 1); MBARRIER_INIT(sb + SM_MBAR + 8, 1); }
    __syncthreads();
    uint32_t tmem;
    asm volatile("ld.shared.b32 %0, [%1];" : "=r"(tmem) : "r"(sb + SM_TMEMP));

    uint32_t l_sw[4];
    const float* a_gp[4]; uint32_t a_sz[4];
    const float* b_gp[4]; uint32_t b_sz[4];
    #pragma unroll
    for (int i = 0; i < 4; i++) {
        int idx = tid + i * 256;
        int r = idx >> 3, c4 = idx & 7;
        uint32_t off = (uint32_t)(r * 128 + c4 * 16);
        l_sw[i] = off ^ ((off >> 3) & 0x70);
        int p = m0 + r;
        a_sz[i] = (p < cnt) ? 16u : 0u;
        a_gp[i] = g_H + ((p < cnt) ? ((size_t)(rowBase + p) * KD + c4 * 4) : 0);
        int n = n0 + r;
        b_sz[i] = (n < NI) ? 16u : 0u;
        b_gp[i] = wp + ((n < NI) ? ((size_t)n * KD + c4 * 4) : 0);
    }

    auto issue_stage = [&](int c) {
        uint32_t base = sb + SM_BUF + (c & 3) * T2_STAGE;
        int k0 = c * 32;
        #pragma unroll
        for (int i = 0; i < 4; i++) {
            cp_async16(base + l_sw[i],           a_gp[i] + k0, a_sz[i]);
            cp_async16(base + TILE16K + l_sw[i], b_gp[i] + k0, b_sz[i]);
        }
        CP_COMMIT();
    };

    issue_stage(0); issue_stage(1); issue_stage(2);

    for (int c = 0; c < NCHUNK; c++) {
        CP_WAIT2();
        __syncthreads();
        if (c == 0) {
            // Patch A-tile col 0 with time lift t = sqrt(1 + sum(sp^2)) from g_part1.
            if (tid < 128) {
                int p = m0 + tid;
                if (p < cnt) {
                    const float* pp = g_part1 + (size_t)(rowBase + p) * 16;
                    float s = 1.0f;
                    #pragma unroll
                    for (int j = 0; j < 16; j++) s += pp[j];
                    uint32_t off = (uint32_t)(tid * 128);
                    uint32_t sw = off ^ ((off >> 3) & 0x70);
                    *(float*)(smem + SM_BUF + sw) = sqrtf(s);
                }
            }
            __syncthreads();
        }
        if (wid == 0) {
            if (elect_one_pred()) {
                FENCE_PROXY_ASYNC_SHARED_CTA();
                uint32_t base = sb + SM_BUF + (c & 3) * T2_STAGE;
                uint64_t ad = MAKE_SMEM_DESC(base);
                uint64_t bd = MAKE_SMEM_DESC(base + TILE16K);
                #pragma unroll
                for (int k = 0; k < 4; k++) {
                    bool acc = (c > 0) || (k > 0);
                    mma_tf32_ss(tmem, ad + k*2, bd + k*2, IDESC_TF32_N128, acc);
                }
                TCGEN05_COMMIT(sb + SM_MBAR + 8 * (c & 1));
            }
        }
        if (c >= 1)
            MBARRIER_WAIT_PARITY(sb + SM_MBAR + 8 * ((c - 1) & 1), ((c - 1) >> 1) & 1);
        if (c + 3 < NCHUNK) issue_stage(c + 3);
        else CP_COMMIT();
    }
    MBARRIER_WAIT_PARITY(sb + SM_MBAR + 8, 1);   // chunk 31
    __syncthreads();
    TCGEN05_FENCE_AFTER();

    float* st = (float*)(smem + SM_BUF);
    float psum = 0.0f;
    for (int cb = 0; cb < 128; cb += 32) {
        if (tid < 128) {
            uint32_t d[32];
            TCGEN05_LD_32X32B_X32(d, tmem + cb);
            TCGEN05_WAIT_LD();
            #pragma unroll
            for (int j = 0; j < 32; j++) {
                float v = __uint_as_float(d[j]);
                st[tid * 33 + j] = v;
                psum += v * v;
            }
        }
        __syncthreads();
        #pragma unroll
        for (int i = 0; i < 16; i++) {
            int l = tid + i * 256;
            int r = l >> 5, cc = l & 31;
            int p = m0 + r;
            int col = n0 + cb + cc;
            if (p < cnt && col < NI)
                g_O[(size_t)(rowBase + p) * KD + 1 + col] = st[r * 33 + cc];
        }
        __syncthreads();
    }
    if (tid < 128) {
        int p = m0 + tid;
        if (p < cnt) {
            int slot = n0 >> 6;
            g_part2[(size_t)(rowBase + p) * 16 + slot]     = psum;
            g_part2[(size_t)(rowBase + p) * 16 + slot + 1] = 0.0f;
        }
    }
    if (wid == 0) TCGEN05_DEALLOC(tmem, 128);
#else
    int n0 = blockIdx.x * 64;
    uint32_t sbuf = smem_to_u32(smem) + 1024;
    __shared__ float s_ps[128];
    if (tid < 128) s_ps[tid] = 0.0f;
    __syncthreads();
    int a_r[4], a_c4[4];
    bool a_v[4];
    const float* a_src[4];
    #pragma unroll
    for (int i = 0; i < 4; i++) {
        int idx = tid + i * 256;
        a_r[i] = idx >> 3; a_c4[i] = idx & 7;
        int p = m0 + a_r[i];
        a_v[i] = (p < cnt);
        a_src[i] = g_H + (a_v[i] ? ((size_t)(rowBase + p) * KD + a_c4[i] * 4) : 0);
    }
    int b_r[2], b_c4[2];
    #pragma unroll
    for (int i = 0; i < 2; i++) {
        int idx = tid + i * 256;
        b_r[i] = idx >> 3; b_c4[i] = idx & 7;
    }
    auto issue_stage = [&](int c) {
        int buf = c % 3;
        uint32_t aB = sbuf + buf * F2_STAGE;
        uint32_t bB = aB + F_A_BYTES;
        int k0 = c * 32;
        #pragma unroll
        for (int i = 0; i < 4; i++)
            cp_async16(aB + (a_r[i] * ASTR + a_c4[i] * 4) * 4, a_src[i] + k0, a_v[i] ? 16u : 0u);
        #pragma unroll
        for (int i = 0; i < 2; i++) {
            int n = n0 + b_r[i];
            bool bv = (n < NI);
            size_t off = bv ? ((size_t)n * KD + k0 + b_c4[i] * 4) : 0;
            cp_async16(bB + (b_r[i] * ASTR + b_c4[i] * 4) * 4, wp + off, bv ? 16u : 0u);
        }
        CP_COMMIT();
    };
    int lane = tid & 31, grp = lane >> 2, tig = lane & 3;
    int mbase = (wid & 3) * 32, nbase = (wid >> 2) * 32;
    float acc[2][4][4];
    #pragma unroll
    for (int mt = 0; mt < 2; mt++)
        #pragma unroll
        for (int nt = 0; nt < 4; nt++)
            #pragma unroll
            for (int q = 0; q < 4; q++) acc[mt][nt][q] = 0.f;
    issue_stage(0); issue_stage(1);
    for (int c = 0; c < NCHUNK; c++) {
        CP_WAIT1();
        __syncthreads();
        if (c == 0) {
            if (tid < 128) {
                int p = m0 + tid;
                if (p < cnt) {
                    const float* pp = g_part1 + (size_t)(rowBase + p) * 16;
                    float s = 1.0f;
                    #pragma unroll
                    for (int j = 0; j < 16; j++) s += pp[j];
                    ((float*)(smem + 1024))[tid * ASTR] = sqrtf(s);
                }
            }
            __syncthreads();
        }
        if (c + 2 < NCHUNK) issue_stage(c + 2);
        else CP_COMMIT();
        int buf = c % 3;
        const float* As = (const float*)(smem + 1024 + buf * F2_STAGE);
        const float* Bs = As + 128 * ASTR;
        #pragma unroll
        for (int ks = 0; ks < 4; ks++) {
            int kk = ks * 8;
            uint32_t a[2][4];
            #pragma unroll
            for (int mt = 0; mt < 2; mt++) {
                int r0 = mbase + mt * 16 + grp;
                a[mt][0] = f2tf32(As[r0 * ASTR + kk + tig]);
                a[mt][1] = f2tf32(As[(r0 + 8) * ASTR + kk + tig]);
                a[mt][2] = f2tf32(As[r0 * ASTR + kk + tig + 4]);
                a[mt][3] = f2tf32(As[(r0 + 8) * ASTR + kk + tig + 4]);
            }
            #pragma unroll
            for (int nt = 0; nt < 4; nt++) {
                int cr = nbase + nt * 8 + grp;
                uint32_t b[2];
                b[0] = f2tf32(Bs[cr * ASTR + kk + tig]);
                b[1] = f2tf32(Bs[cr * ASTR + kk + tig + 4]);
                #pragma unroll
                for (int mt = 0; mt < 2; mt++)
                    MMA_TF32_SYNC(acc[mt][nt], a[mt], b);
            }
        }
        __syncthreads();
    }
    #pragma unroll
    for (int mt = 0; mt < 2; mt++) {
        int pr = mbase + mt * 16 + grp;
        #pragma unroll
        for (int nt = 0; nt < 4; nt++) {
            int col = n0 + nbase + nt * 8 + 2 * tig;
            int p = m0 + pr;
            if (p < cnt) {
                float* orow = g_O + (size_t)(rowBase + p) * KD + 1;
                float add = 0.f;
                if (col < NI)     { orow[col]     = acc[mt][nt][0]; add += acc[mt][nt][0]*acc[mt][nt][0]; }
                if (col + 1 < NI) { orow[col + 1] = acc[mt][nt][1]; add += acc[mt][nt][1]*acc[mt][nt][1]; }
                atomicAdd(&s_ps[pr], add);
            }
            int p2 = p + 8;
            if (p2 < cnt) {
                float* orow = g_O + (size_t)(rowBase + p2) * KD + 1;
                float add = 0.f;
                if (col < NI)     { orow[col]     = acc[mt][nt][2]; add += acc[mt][nt][2]*acc[mt][nt][2]; }
                if (col + 1 < NI) { orow[col + 1] = acc[mt][nt][3]; add += acc[mt][nt][3]*acc[mt][nt][3]; }
                atomicAdd(&s_ps[pr + 8], add);
            }
        }
    }
    __syncthreads();
    if (tid < 128) {
        int p = m0 + tid;
        if (p < cnt) g_part2[(size_t)(rowBase + p) * 16 + (n0 >> 6)] = s_ps[tid];
    }
#endif
}

// ------------------------------- launcher --------------------------------------
extern "C" void kernel_launch(void* const* d_in, const int* in_sizes, int n_in,
                              void* d_out, int out_size) {
    const float* x      = (const float*)d_in[0];
    const float* gate_w = (const float*)d_in[1];
    const float* gate_b = (const float*)d_in[2];
    const float* W1     = (const float*)d_in[3];
    const float* W3     = (const float*)d_in[4];
    const float* W2     = (const float*)d_in[5];
    const float* Ws1    = (const float*)d_in[6];
    const float* Ws3    = (const float*)d_in[7];
    const float* Ws2    = (const float*)d_in[8];
    float* out = (float*)d_out;

    cudaFuncSetAttribute(gemm1_tc, cudaFuncAttributeMaxDynamicSharedMemorySize, SMEM1_TOTAL);
    cudaFuncSetAttribute(gemm2_tc, cudaFuncAttributeMaxDynamicSharedMemorySize, SMEM2_TOTAL);

    gate_kernel<<<TT / 8, 256>>>(x, gate_w, gate_b);
    gemm1_tc<<<dim3(16, 16, 9), 256, SMEM1_TOTAL>>>(x, W1, W3, Ws1, Ws3);
    gemm2_tc<<<dim3(16, 16, 9), 256, SMEM2_TOTAL>>>(W2, Ws2);
    combine_kernel<<<TT / 8, 256>>>(out);
}

// round 17
// speedup vs baseline: 1.0609x; 1.0161x over previous
#include <cuda_runtime.h>
#include <math.h>
#include <stdint.h>

#define TT 2048
#define DD 1024
#define EE 8
#define NI 1023
#define KD 1024

#define ROWS_ROUTED (EE * TT)
#define SHARED_BASE ROWS_ROUTED
#define TOTAL_ROWS  (ROWS_ROUTED + TT)

#if defined(__CUDA_ARCH_FEAT_SM103_ALL) || defined(__CUDA_ARCH_FEAT_SM100_ALL) || defined(__CUDA_ARCH_FEAT_SM101_ALL)
#define HAS_TCGEN05 1
#else
#define HAS_TCGEN05 0
#endif

// ------------------- device scratch -------------------
__device__ float g_H[(size_t)TOTAL_ROWS * KD];
__device__ float g_O[(size_t)TOTAL_ROWS * KD];
__device__ float g_part1[(size_t)TOTAL_ROWS * 16];
__device__ float g_part2[(size_t)TOTAL_ROWS * 16];
__device__ int   g_cnt[EE];                          // zero at load; re-zeroed by combine
__device__ int   g_bucket[ROWS_ROUTED];
__device__ int   g_rowOf[TT];
__device__ float g_wgt[TT];

// ------------------------------ helpers -----------------------------------------
__device__ __forceinline__ uint32_t smem_to_u32(const void* p) {
    uint32_t a;
    asm("{ .reg .u64 t; cvta.to.shared.u64 t, %1; cvt.u32.u64 %0, t; }" : "=r"(a) : "l"(p));
    return a;
}
__device__ __forceinline__ uint32_t f2tf32(float f) {
    uint32_t o; asm("cvt.rna.tf32.f32 %0, %1;" : "=r"(o) : "f"(f)); return o;
}
__device__ __forceinline__ float silu_mul(float v1, float v3) {
    return v1 * v3 / (1.0f + __expf(-v1));
}
__device__ __forceinline__ void cp_async16(uint32_t smem_addr, const void* gptr, uint32_t src_size) {
    asm volatile("cp.async.cg.shared.global [%0], [%1], 16, %2;"
                 :: "r"(smem_addr), "l"(gptr), "r"(src_size) : "memory");
}
#define CP_COMMIT() asm volatile("cp.async.commit_group;" ::: "memory")
#define CP_WAIT1()  asm volatile("cp.async.wait_group 1;" ::: "memory")
#define CP_WAIT2()  asm volatile("cp.async.wait_group 2;" ::: "memory")

#define MBARRIER_INIT(mbar, count) \
    asm volatile("mbarrier.init.shared.b64 [%0], %1;" \
        :: "r"((uint32_t)(mbar)), "r"((uint32_t)(count)) : "memory")
#define MBARRIER_WAIT_PARITY(mbar_smem_addr, phase_parity) do { \
    uint32_t _mbar = (uint32_t)(mbar_smem_addr); \
    uint32_t _parity = (uint32_t)(phase_parity); \
    uint32_t _done; \
    asm volatile("{\n\t.reg .pred p;\n\t" \
        "mbarrier.try_wait.parity.acquire.cta.shared::cta.b64 p, [%1], %2;\n\t" \
        "selp.b32 %0, 1, 0, p;\n\t}" : "=r"(_done) : "r"(_mbar), "r"(_parity) : "memory"); \
    if (!_done) { \
        asm volatile("{\n\t.reg .pred P1;\n\t" \
            "WAIT_LOOP_%=:\n\t" \
            "mbarrier.try_wait.parity.acquire.cta.shared::cta.b64 P1, [%0], %1, 0x989680;\n\t" \
            "@P1 bra.uni WAIT_DONE_%=;\n\t" \
            "bra.uni WAIT_LOOP_%=;\n\t" \
            "WAIT_DONE_%=:\n\t}" :: "r"(_mbar), "r"(_parity) : "memory"); \
    } \
} while(0)

#if HAS_TCGEN05
__device__ __forceinline__ uint32_t elect_one_pred() {
    uint32_t pred;
    asm volatile("{\n\t.reg .pred p;\n\telect.sync _|p, 0xFFFFFFFF;\n\t"
                 "selp.b32 %0, 1, 0, p;\n\t}" : "=r"(pred));
    return pred;
}
#define TCGEN05_ALLOC(smem_result_addr, nCols) \
    asm volatile("tcgen05.alloc.cta_group::1.sync.aligned.shared::cta.b32 [%0], %1;" \
        :: "r"((uint32_t)(smem_result_addr)), "r"((uint32_t)(nCols)) : "memory")
#define TCGEN05_DEALLOC(tmem_addr, nCols) \
    asm volatile("tcgen05.dealloc.cta_group::1.sync.aligned.b32 %0, %1;" \
        :: "r"(tmem_addr), "r"((uint32_t)(nCols)))
#define TCGEN05_COMMIT(mbar_smem_addr) \
    asm volatile("tcgen05.commit.cta_group::1.mbarrier::arrive::one.shared::cluster.b64 [%0];" \
        :: "r"((uint32_t)(mbar_smem_addr)) : "memory")
#define TCGEN05_WAIT_LD() asm volatile("tcgen05.wait::ld.sync.aligned;" ::: "memory")
#define TCGEN05_FENCE_AFTER() asm volatile("tcgen05.fence::after_thread_sync;" ::: "memory")
#define FENCE_PROXY_ASYNC_SHARED_CTA() asm volatile("fence.proxy.async.shared::cta;" ::: "memory")
#define TCGEN05_LD_32X32B_X32(r, tmem_addr) \
    asm volatile("tcgen05.ld.sync.aligned.32x32b.x32.b32 " \
        "{%0, %1, %2, %3, %4, %5, %6, %7, " \
        " %8, %9, %10, %11, %12, %13, %14, %15, " \
        " %16, %17, %18, %19, %20, %21, %22, %23, " \
        " %24, %25, %26, %27, %28, %29, %30, %31}, [%32];" \
        : "=r"((r)[0]),  "=r"((r)[1]),  "=r"((r)[2]),  "=r"((r)[3]), \
          "=r"((r)[4]),  "=r"((r)[5]),  "=r"((r)[6]),  "=r"((r)[7]), \
          "=r"((r)[8]),  "=r"((r)[9]),  "=r"((r)[10]), "=r"((r)[11]), \
          "=r"((r)[12]), "=r"((r)[13]), "=r"((r)[14]), "=r"((r)[15]), \
          "=r"((r)[16]), "=r"((r)[17]), "=r"((r)[18]), "=r"((r)[19]), \
          "=r"((r)[20]), "=r"((r)[21]), "=r"((r)[22]), "=r"((r)[23]), \
          "=r"((r)[24]), "=r"((r)[25]), "=r"((r)[26]), "=r"((r)[27]), \
          "=r"((r)[28]), "=r"((r)[29]), "=r"((r)[30]), "=r"((r)[31]) \
        : "r"(tmem_addr))

static constexpr uint64_t SMEM_DESC_BASE_SW128 =
    (uint64_t(2) << 61) | (uint64_t(1) << 46) | (uint64_t(64) << 32) | (uint64_t(1) << 16);
#define MAKE_SMEM_DESC(base_addr) \
    (SMEM_DESC_BASE_SW128 | ((uint64_t)((base_addr) >> 4) & 0x3FFF))
#define IDESC_TF32_N128 ((1u<<4) | (2u<<7) | (2u<<10) | (16u<<17) | (8u<<24))
#define IDESC_TF32_N256 ((1u<<4) | (2u<<7) | (2u<<10) | (32u<<17) | (8u<<24))

__device__ __forceinline__ void mma_tf32_ss(uint32_t d_tmem, uint64_t a_desc,
                                            uint64_t b_desc, uint32_t idesc, bool acc) {
    uint32_t en = acc ? 1u : 0u;
    asm volatile(
        "{\n\t.reg .pred p;\n\tsetp.ne.u32 p, %5, 0;\n\t"
        "tcgen05.mma.cta_group::1.kind::tf32 [%0], %1, %2, %3, {%4, %4, %4, %4}, p;\n\t}"
        :: "r"(d_tmem), "l"(a_desc), "l"(b_desc), "r"(idesc), "r"(0u), "r"(en)
        : "memory");
}
#endif // HAS_TCGEN05

#define MMA_TF32_SYNC(d, a, b) \
    asm volatile("mma.sync.aligned.m16n8k8.row.col.f32.tf32.tf32.f32 " \
        "{%0,%1,%2,%3}, {%4,%5,%6,%7}, {%8,%9}, {%0,%1,%2,%3};" \
        : "+f"((d)[0]), "+f"((d)[1]), "+f"((d)[2]), "+f"((d)[3]) \
        : "r"((a)[0]), "r"((a)[1]), "r"((a)[2]), "r"((a)[3]), \
          "r"((b)[0]), "r"((b)[1]))

// ------------------------------- small kernels ----------------------------------
__device__ __forceinline__ float warp_reduce_sum(float v) {
    #pragma unroll
    for (int o = 16; o; o >>= 1) v += __shfl_xor_sync(0xffffffffu, v, o);
    return v;
}

__global__ void gate_kernel(const float* __restrict__ x,
                            const float* __restrict__ gate_w,
                            const float* __restrict__ gate_b) {
    int tid = threadIdx.x;
    int w = tid >> 5, lane = tid & 31;
    __shared__ float sl[8][8];

    float gw_reg[32];
    const float* gr = gate_w + (size_t)w * NI;
    #pragma unroll
    for (int i = 0; i < 32; i++) {
        int c = lane + 32 * i;
        gw_reg[i] = (c < NI) ? gr[c] : 0.0f;
    }
    #pragma unroll
    for (int j = 0; j < 8; j++) {
        int t = blockIdx.x * 8 + j;
        const float* xr = x + (size_t)t * DD + 1;
        float s = 0.0f;
        #pragma unroll
        for (int i = 0; i < 32; i++) {
            int c = lane + 32 * i;
            if (c < NI) s += gw_reg[i] * xr[c];
        }
        s = warp_reduce_sum(s);
        if (lane == 0) sl[j][w] = s;
    }
    __syncthreads();
    if (tid < 8) {
        int t = blockIdx.x * 8 + tid;
        float m = sl[tid][0];
        #pragma unroll
        for (int e = 1; e < EE; e++) m = fmaxf(m, sl[tid][e]);
        float ex[EE], den = 0.0f;
        #pragma unroll
        for (int e = 0; e < EE; e++) { ex[e] = expf(sl[tid][e] - m); den += ex[e]; }
        float inv = 1.0f / den;
        float best = -1e30f; int bi = 0;
        #pragma unroll
        for (int e = 0; e < EE; e++) {
            float biased = ex[e] * inv + gate_b[e];
            if (biased > best) { best = biased; bi = e; }
        }
        g_wgt[t] = ex[bi] * inv;
        int p = atomicAdd(&g_cnt[bi], 1);
        g_bucket[bi * TT + p] = t;
        g_rowOf[t] = bi * TT + p;
    }
}

// combine: er[0], zr[0] computed inline from g_part2 partials; re-zeros g_cnt.
__global__ void combine_kernel(float* __restrict__ out) {
    int lane = threadIdx.x & 31;
    int t = blockIdx.x * 8 + (threadIdx.x >> 5);
    int rr = g_rowOf[t];
    int zrow = SHARED_BASE + t;
    float wgt = g_wgt[t];
    const float* zr = g_O + (size_t)zrow * KD;
    const float* er = g_O + (size_t)rr * KD;

    float v = (lane < 16) ? g_part2[(size_t)rr * 16 + lane]
                          : g_part2[(size_t)zrow * 16 + (lane - 16)];
    #pragma unroll
    for (int o = 8; o; o >>= 1) v += __shfl_xor_sync(0xffffffffu, v, o);
    float er0 = sqrtf(1.0f + __shfl_sync(0xffffffffu, v, 0));
    float zr0 = sqrtf(1.0f + __shfl_sync(0xffffffffu, v, 16));

    float c0 = zr0 + 2.0f * (1.0f + wgt * er0);
    float comb[32];
    float ss = 0.0f;
    #pragma unroll
    for (int i = 0; i < 32; i++) {
        int d = lane + 32 * i;
        if (d == 0) {
            comb[i] = c0;
        } else {
            float cv = zr[d] + 2.0f * wgt * er[d];
            comb[i] = cv;
            ss += cv * cv;
        }
    }
    ss = warp_reduce_sum(ss);
    float li = ss - c0 * c0;
    float scale = rsqrtf(fmaxf(fabsf(li), 1e-8f));
    #pragma unroll
    for (int i = 0; i < 32; i++)
        out[(size_t)t * DD + lane + 32 * i] = comb[i] * scale;

    if (blockIdx.x == 0 && threadIdx.x < EE) g_cnt[threadIdx.x] = 0;
}

// ------------------------------ smem layout --------------------------------------
#define SM_TOKS  0
#define SM_MBAR  512
#define SM_TMEMP 528
#define SM_BUF   1024
#define TILE16K  16384
#define T1_STAGE (3 * TILE16K)
#define T2_STAGE (2 * TILE16K)
#define STAGES   4
#define SMEM1_TOTAL (SM_BUF + STAGES * T1_STAGE)   // 197632
#define SMEM2_TOTAL (SM_BUF + STAGES * T2_STAGE)   // 132096
#define NCHUNK 32

// fallback layout constants (non-'a' pass only)
#define ASTR   36
#define F_A_BYTES (128 * ASTR * 4)
#define F_B_BYTES (64  * ASTR * 4)
#define F1_STAGE (F_A_BYTES + 2 * F_B_BYTES)
#define F2_STAGE (F_A_BYTES + F_B_BYTES)

// ------------------------------ GEMM 1 ------------------------------------------
__global__ void __launch_bounds__(256) gemm1_tc(
    const float* __restrict__ x,
    const float* __restrict__ W1, const float* __restrict__ W3,
    const float* __restrict__ Ws1, const float* __restrict__ Ws3)
{
    extern __shared__ char smem[];
    int tid = threadIdx.x;
    int wid = tid >> 5;

    int e = blockIdx.z;
    int cnt; const float *w1p, *w3p; int rowBase;
    if (e < EE) {
        cnt = g_cnt[e];
        w1p = W1 + (size_t)e * NI * KD;
        w3p = W3 + (size_t)e * NI * KD;
        rowBase = e * TT;
    } else {
        cnt = TT; w1p = Ws1; w3p = Ws3; rowBase = SHARED_BASE;
    }
    int m0 = blockIdx.y * 128;
    if (m0 >= cnt) return;

#if HAS_TCGEN05
    if (blockIdx.x & 1) return;
    int n0 = (blockIdx.x >> 1) * 128;
    uint32_t sb = smem_to_u32(smem);

    int* toks = (int*)(smem + SM_TOKS);
    if (tid < 128) {
        int p = m0 + tid;
        toks[tid] = (p < cnt) ? ((e < EE) ? g_bucket[e * TT + p] : p) : -1;
    }
    if (wid == 0) TCGEN05_ALLOC(sb + SM_TMEMP, 256);
    if (tid == 0) { MBARRIER_INIT(sb + SM_MBAR, 1); MBARRIER_INIT(sb + SM_MBAR + 8, 1); }
    __syncthreads();
    uint32_t tmem;
    asm volatile("ld.shared.b32 %0, [%1];" : "=r"(tmem) : "r"(sb + SM_TMEMP));

    uint32_t l_sw[4];
    const float* a_gp[4]; uint32_t a_sz[4];
    const float* b1_gp[4]; const float* b3_gp[4]; uint32_t b_sz[4];
    #pragma unroll
    for (int i = 0; i < 4; i++) {
        int idx = tid + i * 256;
        int r = idx >> 3, c4 = idx & 7;
        uint32_t off = (uint32_t)(r * 128 + c4 * 16);
        l_sw[i] = off ^ ((off >> 3) & 0x70);
        int tok = toks[r];
        a_sz[i] = (tok >= 0) ? 16u : 0u;
        a_gp[i] = x + ((tok >= 0) ? ((size_t)tok * DD + c4 * 4) : 0);
        int n = n0 + r;
        b_sz[i] = (n < NI) ? 16u : 0u;
        size_t boff = (n < NI) ? ((size_t)n * KD + c4 * 4) : 0;
        b1_gp[i] = w1p + boff;
        b3_gp[i] = w3p + boff;
    }

    auto issue_stage = [&](int c) {
        uint32_t base = sb + SM_BUF + (c & 3) * T1_STAGE;
        int k0 = c * 32;
        #pragma unroll
        for (int i = 0; i < 4; i++) {
            cp_async16(base + l_sw[i],                a_gp[i] + k0, a_sz[i]);
            cp_async16(base + TILE16K + l_sw[i],      b1_gp[i] + k0, b_sz[i]);
            cp_async16(base + 2 * TILE16K + l_sw[i],  b3_gp[i] + k0, b_sz[i]);
        }
        CP_COMMIT();
    };

    issue_stage(0); issue_stage(1); issue_stage(2);

    for (int c = 0; c < NCHUNK; c++) {
        CP_WAIT2();
        __syncthreads();
        if (wid == 0) {
            if (elect_one_pred()) {
                FENCE_PROXY_ASYNC_SHARED_CTA();
                uint32_t base = sb + SM_BUF + (c & 3) * T1_STAGE;
                uint64_t ad = MAKE_SMEM_DESC(base);
                // B1(16KB) and B3(16KB) are adjacent: one contiguous 256-row tile.
                // Single N=256 MMA computes D = A @ [B1;B3]^T:
                //   TMEM cols 0..127 = D1, cols 128..255 = D3 (same layout as before).
                uint64_t bd = MAKE_SMEM_DESC(base + TILE16K);
                #pragma unroll
                for (int k = 0; k < 4; k++) {
                    bool acc = (c > 0) || (k > 0);
                    mma_tf32_ss(tmem, ad + k*2, bd + k*2, IDESC_TF32_N256, acc);
                }
                TCGEN05_COMMIT(sb + SM_MBAR + 8 * (c & 1));
            }
        }
        if (c >= 1)
            MBARRIER_WAIT_PARITY(sb + SM_MBAR + 8 * ((c - 1) & 1), ((c - 1) >> 1) & 1);
        if (c + 3 < NCHUNK) issue_stage(c + 3);
        else CP_COMMIT();
    }
    MBARRIER_WAIT_PARITY(sb + SM_MBAR + 8, 1);   // chunk 31
    __syncthreads();
    TCGEN05_FENCE_AFTER();

    // Epilogue: sp = silu(d1)*d3 with fused row-partials of sp^2
    float* st = (float*)(smem + SM_BUF);
    float psum = 0.0f;
    for (int cb = 0; cb < 128; cb += 32) {
        if (tid < 128) {
            uint32_t d1[32], d2[32];
            TCGEN05_LD_32X32B_X32(d1, tmem + cb);
            TCGEN05_LD_32X32B_X32(d2, tmem + 128 + cb);
            TCGEN05_WAIT_LD();
            #pragma unroll
            for (int j = 0; j < 32; j++) {
                float sp = silu_mul(__uint_as_float(d1[j]), __uint_as_float(d2[j]));
                st[tid * 33 + j] = sp;
                psum += sp * sp;
            }
        }
        __syncthreads();
        #pragma unroll
        for (int i = 0; i < 16; i++) {
            int l = tid + i * 256;
            int r = l >> 5, cc = l & 31;
            int p = m0 + r;
            int col = n0 + cb + cc;
            if (p < cnt && col < NI)
                g_H[(size_t)(rowBase + p) * KD + 1 + col] = st[r * 33 + cc];
        }
        __syncthreads();
    }
    if (tid < 128) {
        int p = m0 + tid;
        if (p < cnt) {
            int slot = n0 >> 6;
            g_part1[(size_t)(rowBase + p) * 16 + slot]     = psum;
            g_part1[(size_t)(rowBase + p) * 16 + slot + 1] = 0.0f;
        }
    }
    if (wid == 0) TCGEN05_DEALLOC(tmem, 256);
#else
    // ---------------- fallback: pipelined mma.sync (compute_103 pass only) --------
    int n0 = blockIdx.x * 64;
    int* toks = (int*)smem;
    uint32_t sbuf = smem_to_u32(smem) + 1024;
    __shared__ float s_ps[128];
    if (tid < 128) {
        int p = m0 + tid;
        toks[tid] = (p < cnt) ? ((e < EE) ? g_bucket[e * TT + p] : p) : -1;
        s_ps[tid] = 0.0f;
    }
    __syncthreads();
    int a_r[4], a_c4[4], a_tok[4];
    #pragma unroll
    for (int i = 0; i < 4; i++) {
        int idx = tid + i * 256;
        a_r[i] = idx >> 3; a_c4[i] = idx & 7; a_tok[i] = toks[a_r[i]];
    }
    int b_r[2], b_c4[2];
    #pragma unroll
    for (int i = 0; i < 2; i++) {
        int idx = tid + i * 256;
        b_r[i] = idx >> 3; b_c4[i] = idx & 7;
    }
    auto issue_stage = [&](int c) {
        int buf = c % 3;
        uint32_t aB  = sbuf + buf * F1_STAGE;
        uint32_t b1B = aB + F_A_BYTES;
        uint32_t b3B = b1B + F_B_BYTES;
        int k0 = c * 32;
        #pragma unroll
        for (int i = 0; i < 4; i++) {
            int tok = a_tok[i];
            const float* src = x + ((tok >= 0) ? ((size_t)tok * DD + k0 + a_c4[i] * 4) : 0);
            cp_async16(aB + (a_r[i] * ASTR + a_c4[i] * 4) * 4, src, (tok >= 0) ? 16u : 0u);
        }
        #pragma unroll
        for (int i = 0; i < 2; i++) {
            int n = n0 + b_r[i];
            bool bv = (n < NI);
            size_t off = bv ? ((size_t)n * KD + k0 + b_c4[i] * 4) : 0;
            uint32_t so = (b_r[i] * ASTR + b_c4[i] * 4) * 4;
            cp_async16(b1B + so, w1p + off, bv ? 16u : 0u);
            cp_async16(b3B + so, w3p + off, bv ? 16u : 0u);
        }
        CP_COMMIT();
    };
    int lane = tid & 31, grp = lane >> 2, tig = lane & 3;
    int mbase = (wid & 3) * 32, nbase = (wid >> 2) * 32;
    float c1[2][4][4], c3[2][4][4];
    #pragma unroll
    for (int mt = 0; mt < 2; mt++)
        #pragma unroll
        for (int nt = 0; nt < 4; nt++)
            #pragma unroll
            for (int q = 0; q < 4; q++) { c1[mt][nt][q] = 0.f; c3[mt][nt][q] = 0.f; }
    issue_stage(0); issue_stage(1);
    for (int c = 0; c < NCHUNK; c++) {
        CP_WAIT1();
        __syncthreads();
        if (c + 2 < NCHUNK) issue_stage(c + 2);
        else CP_COMMIT();
        int buf = c % 3;
        const float* As  = (const float*)(smem + 1024 + buf * F1_STAGE);
        const float* B1s = As + 128 * ASTR;
        const float* B3s = B1s + 64 * ASTR;
        #pragma unroll
        for (int ks = 0; ks < 4; ks++) {
            int kk = ks * 8;
            uint32_t a[2][4];
            #pragma unroll
            for (int mt = 0; mt < 2; mt++) {
                int r0 = mbase + mt * 16 + grp;
                a[mt][0] = f2tf32(As[r0 * ASTR + kk + tig]);
                a[mt][1] = f2tf32(As[(r0 + 8) * ASTR + kk + tig]);
                a[mt][2] = f2tf32(As[r0 * ASTR + kk + tig + 4]);
                a[mt][3] = f2tf32(As[(r0 + 8) * ASTR + kk + tig + 4]);
            }
            uint32_t b1[4][2], b3[4][2];
            #pragma unroll
            for (int nt = 0; nt < 4; nt++) {
                int cr = nbase + nt * 8 + grp;
                b1[nt][0] = f2tf32(B1s[cr * ASTR + kk + tig]);
                b1[nt][1] = f2tf32(B1s[cr * ASTR + kk + tig + 4]);
                b3[nt][0] = f2tf32(B3s[cr * ASTR + kk + tig]);
                b3[nt][1] = f2tf32(B3s[cr * ASTR + kk + tig + 4]);
            }
            #pragma unroll
            for (int mt = 0; mt < 2; mt++)
                #pragma unroll
                for (int nt = 0; nt < 4; nt++) {
                    MMA_TF32_SYNC(c1[mt][nt], a[mt], b1[nt]);
                    MMA_TF32_SYNC(c3[mt][nt], a[mt], b3[nt]);
                }
        }
        __syncthreads();
    }
    #pragma unroll
    for (int mt = 0; mt < 2; mt++) {
        int pr = mbase + mt * 16 + grp;
        #pragma unroll
        for (int nt = 0; nt < 4; nt++) {
            int col = n0 + nbase + nt * 8 + 2 * tig;
            int p = m0 + pr;
            if (p < cnt) {
                float* hrow = g_H + (size_t)(rowBase + p) * KD + 1;
                float s0 = silu_mul(c1[mt][nt][0], c3[mt][nt][0]);
                float s1 = silu_mul(c1[mt][nt][1], c3[mt][nt][1]);
                float add = 0.f;
                if (col < NI)     { hrow[col]     = s0; add += s0 * s0; }
                if (col + 1 < NI) { hrow[col + 1] = s1; add += s1 * s1; }
                atomicAdd(&s_ps[pr], add);
            }
            int p2 = p + 8;
            if (p2 < cnt) {
                float* hrow = g_H + (size_t)(rowBase + p2) * KD + 1;
                float s2 = silu_mul(c1[mt][nt][2], c3[mt][nt][2]);
                float s3 = silu_mul(c1[mt][nt][3], c3[mt][nt][3]);
                float add = 0.f;
                if (col < NI)     { hrow[col]     = s2; add += s2 * s2; }
                if (col + 1 < NI) { hrow[col + 1] = s3; add += s3 * s3; }
                atomicAdd(&s_ps[pr + 8], add);
            }
        }
    }
    __syncthreads();
    if (tid < 128) {
        int p = m0 + tid;
        if (p < cnt) g_part1[(size_t)(rowBase + p) * 16 + (n0 >> 6)] = s_ps[tid];
    }
#endif
}

// ------------------------------ GEMM 2 ------------------------------------------
__global__ void __launch_bounds__(256) gemm2_tc(
    const float* __restrict__ W2, const float* __restrict__ Ws2)
{
    extern __shared__ char smem[];
    int tid = threadIdx.x;
    int wid = tid >> 5;

    int e = blockIdx.z;
    int cnt; const float* wp; int rowBase;
    if (e < EE) { cnt = g_cnt[e]; wp = W2 + (size_t)e * NI * KD; rowBase = e * TT; }
    else        { cnt = TT;       wp = Ws2;                      rowBase = SHARED_BASE; }
    int m0 = blockIdx.y * 128;
    if (m0 >= cnt) return;

#if HAS_TCGEN05
    if (blockIdx.x & 1) return;
    int n0 = (blockIdx.x >> 1) * 128;
    uint32_t sb = smem_to_u32(smem);

    if (wid == 0) TCGEN05_ALLOC(sb + SM_TMEMP, 128);
    if (tid == 0) { MBARRIER_INIT(sb + SM_MBAR, 1); MBARRIER_INIT(sb + SM_MBAR + 8, 1); }
    __syncthreads();
    uint32_t tmem;
    asm volatile("ld.shared.b32 %0, [%1];" : "=r"(tmem) : "r"(sb + SM_TMEMP));

    uint32_t l_sw[4];
    const float* a_gp[4]; uint32_t a_sz[4];
    const float* b_gp[4]; uint32_t b_sz[4];
    #pragma unroll
    for (int i = 0; i < 4; i++) {
        int idx = tid + i * 256;
        int r = idx >> 3, c4 = idx & 7;
        uint32_t off = (uint32_t)(r * 128 + c4 * 16);
        l_sw[i] = off ^ ((off >> 3) & 0x70);
        int p = m0 + r;
        a_sz[i] = (p < cnt) ? 16u : 0u;
        a_gp[i] = g_H + ((p < cnt) ? ((size_t)(rowBase + p) * KD + c4 * 4) : 0);
        int n = n0 + r;
        b_sz[i] = (n < NI) ? 16u : 0u;
        b_gp[i] = wp + ((n < NI) ? ((size_t)n * KD + c4 * 4) : 0);
    }

    auto issue_stage = [&](int c) {
        uint32_t base = sb + SM_BUF + (c & 3) * T2_STAGE;
        int k0 = c * 32;
        #pragma unroll
        for (int i = 0; i < 4; i++) {
            cp_async16(base + l_sw[i],           a_gp[i] + k0, a_sz[i]);
            cp_async16(base + TILE16K + l_sw[i], b_gp[i] + k0, b_sz[i]);
        }
        CP_COMMIT();
    };

    issue_stage(0); issue_stage(1); issue_stage(2);

    for (int c = 0; c < NCHUNK; c++) {
        CP_WAIT2();
        __syncthreads();
        if (c == 0) {
            // Patch A-tile col 0 with time lift t = sqrt(1 + sum(sp^2)) from g_part1.
            if (tid < 128) {
                int p = m0 + tid;
                if (p < cnt) {
                    const float* pp = g_part1 + (size_t)(rowBase + p) * 16;
                    float s = 1.0f;
                    #pragma unroll
                    for (int j = 0; j < 16; j++) s += pp[j];
                    uint32_t off = (uint32_t)(tid * 128);
                    uint32_t sw = off ^ ((off >> 3) & 0x70);
                    *(float*)(smem + SM_BUF + sw) = sqrtf(s);
                }
            }
            __syncthreads();
        }
        if (wid == 0) {
            if (elect_one_pred()) {
                FENCE_PROXY_ASYNC_SHARED_CTA();
                uint32_t base = sb + SM_BUF + (c & 3) * T2_STAGE;
                uint64_t ad = MAKE_SMEM_DESC(base);
                uint64_t bd = MAKE_SMEM_DESC(base + TILE16K);
                #pragma unroll
                for (int k = 0; k < 4; k++) {
                    bool acc = (c > 0) || (k > 0);
                    mma_tf32_ss(tmem, ad + k*2, bd + k*2, IDESC_TF32_N128, acc);
                }
                TCGEN05_COMMIT(sb + SM_MBAR + 8 * (c & 1));
            }
        }
        if (c >= 1)
            MBARRIER_WAIT_PARITY(sb + SM_MBAR + 8 * ((c - 1) & 1), ((c - 1) >> 1) & 1);
        if (c + 3 < NCHUNK) issue_stage(c + 3);
        else CP_COMMIT();
    }
    MBARRIER_WAIT_PARITY(sb + SM_MBAR + 8, 1);   // chunk 31
    __syncthreads();
    TCGEN05_FENCE_AFTER();

    float* st = (float*)(smem + SM_BUF);
    float psum = 0.0f;
    for (int cb = 0; cb < 128; cb += 32) {
        if (tid < 128) {
            uint32_t d[32];
            TCGEN05_LD_32X32B_X32(d, tmem + cb);
            TCGEN05_WAIT_LD();
            #pragma unroll
            for (int j = 0; j < 32; j++) {
                float v = __uint_as_float(d[j]);
                st[tid * 33 + j] = v;
                psum += v * v;
            }
        }
        __syncthreads();
        #pragma unroll
        for (int i = 0; i < 16; i++) {
            int l = tid + i * 256;
            int r = l >> 5, cc = l & 31;
            int p = m0 + r;
            int col = n0 + cb + cc;
            if (p < cnt && col < NI)
                g_O[(size_t)(rowBase + p) * KD + 1 + col] = st[r * 33 + cc];
        }
        __syncthreads();
    }
    if (tid < 128) {
        int p = m0 + tid;
        if (p < cnt) {
            int slot = n0 >> 6;
            g_part2[(size_t)(rowBase + p) * 16 + slot]     = psum;
            g_part2[(size_t)(rowBase + p) * 16 + slot + 1] = 0.0f;
        }
    }
    if (wid == 0) TCGEN05_DEALLOC(tmem, 128);
#else
    int n0 = blockIdx.x * 64;
    uint32_t sbuf = smem_to_u32(smem) + 1024;
    __shared__ float s_ps[128];
    if (tid < 128) s_ps[tid] = 0.0f;
    __syncthreads();
    int a_r[4], a_c4[4];
    bool a_v[4];
    const float* a_src[4];
    #pragma unroll
    for (int i = 0; i < 4; i++) {
        int idx = tid + i * 256;
        a_r[i] = idx >> 3; a_c4[i] = idx & 7;
        int p = m0 + a_r[i];
        a_v[i] = (p < cnt);
        a_src[i] = g_H + (a_v[i] ? ((size_t)(rowBase + p) * KD + a_c4[i] * 4) : 0);
    }
    int b_r[2], b_c4[2];
    #pragma unroll
    for (int i = 0; i < 2; i++) {
        int idx = tid + i * 256;
        b_r[i] = idx >> 3; b_c4[i] = idx & 7;
    }
    auto issue_stage = [&](int c) {
        int buf = c % 3;
        uint32_t aB = sbuf + buf * F2_STAGE;
        uint32_t bB = aB + F_A_BYTES;
        int k0 = c * 32;
        #pragma unroll
        for (int i = 0; i < 4; i++)
            cp_async16(aB + (a_r[i] * ASTR + a_c4[i] * 4) * 4, a_src[i] + k0, a_v[i] ? 16u : 0u);
        #pragma unroll
        for (int i = 0; i < 2; i++) {
            int n = n0 + b_r[i];
            bool bv = (n < NI);
            size_t off = bv ? ((size_t)n * KD + k0 + b_c4[i] * 4) : 0;
            cp_async16(bB + (b_r[i] * ASTR + b_c4[i] * 4) * 4, wp + off, bv ? 16u : 0u);
        }
        CP_COMMIT();
    };
    int lane = tid & 31, grp = lane >> 2, tig = lane & 3;
    int mbase = (wid & 3) * 32, nbase = (wid >> 2) * 32;
    float acc[2][4][4];
    #pragma unroll
    for (int mt = 0; mt < 2; mt++)
        #pragma unroll
        for (int nt = 0; nt < 4; nt++)
            #pragma unroll
            for (int q = 0; q < 4; q++) acc[mt][nt][q] = 0.f;
    issue_stage(0); issue_stage(1);
    for (int c = 0; c < NCHUNK; c++) {
        CP_WAIT1();
        __syncthreads();
        if (c == 0) {
            if (tid < 128) {
                int p = m0 + tid;
                if (p < cnt) {
                    const float* pp = g_part1 + (size_t)(rowBase + p) * 16;
                    float s = 1.0f;
                    #pragma unroll
                    for (int j = 0; j < 16; j++) s += pp[j];
                    ((float*)(smem + 1024))[tid * ASTR] = sqrtf(s);
                }
            }
            __syncthreads();
        }
        if (c + 2 < NCHUNK) issue_stage(c + 2);
        else CP_COMMIT();
        int buf = c % 3;
        const float* As = (const float*)(smem + 1024 + buf * F2_STAGE);
        const float* Bs = As + 128 * ASTR;
        #pragma unroll
        for (int ks = 0; ks < 4; ks++) {
            int kk = ks * 8;
            uint32_t a[2][4];
            #pragma unroll
            for (int mt = 0; mt < 2; mt++) {
                int r0 = mbase + mt * 16 + grp;
                a[mt][0] = f2tf32(As[r0 * ASTR + kk + tig]);
                a[mt][1] = f2tf32(As[(r0 + 8) * ASTR + kk + tig]);
                a[mt][2] = f2tf32(As[r0 * ASTR + kk + tig + 4]);
                a[mt][3] = f2tf32(As[(r0 + 8) * ASTR + kk + tig + 4]);
            }
            #pragma unroll
            for (int nt = 0; nt < 4; nt++) {
                int cr = nbase + nt * 8 + grp;
                uint32_t b[2];
                b[0] = f2tf32(Bs[cr * ASTR + kk + tig]);
                b[1] = f2tf32(Bs[cr * ASTR + kk + tig + 4]);
                #pragma unroll
                for (int mt = 0; mt < 2; mt++)
                    MMA_TF32_SYNC(acc[mt][nt], a[mt], b);
            }
        }
        __syncthreads();
    }
    #pragma unroll
    for (int mt = 0; mt < 2; mt++) {
        int pr = mbase + mt * 16 + grp;
        #pragma unroll
        for (int nt = 0; nt < 4; nt++) {
            int col = n0 + nbase + nt * 8 + 2 * tig;
            int p = m0 + pr;
            if (p < cnt) {
                float* orow = g_O + (size_t)(rowBase + p) * KD + 1;
                float add = 0.f;
                if (col < NI)     { orow[col]     = acc[mt][nt][0]; add += acc[mt][nt][0]*acc[mt][nt][0]; }
                if (col + 1 < NI) { orow[col + 1] = acc[mt][nt][1]; add += acc[mt][nt][1]*acc[mt][nt][1]; }
                atomicAdd(&s_ps[pr], add);
            }
            int p2 = p + 8;
            if (p2 < cnt) {
                float* orow = g_O + (size_t)(rowBase + p2) * KD + 1;
                float add = 0.f;
                if (col < NI)     { orow[col]     = acc[mt][nt][2]; add += acc[mt][nt][2]*acc[mt][nt][2]; }
                if (col + 1 < NI) { orow[col + 1] = acc[mt][nt][3]; add += acc[mt][nt][3]*acc[mt][nt][3]; }
                atomicAdd(&s_ps[pr + 8], add);
            }
        }
    }
    __syncthreads();
    if (tid < 128) {
        int p = m0 + tid;
        if (p < cnt) g_part2[(size_t)(rowBase + p) * 16 + (n0 >> 6)] = s_ps[tid];
    }
#endif
}

// ------------------------------- launcher --------------------------------------
extern "C" void kernel_launch(void* const* d_in, const int* in_sizes, int n_in,
                              void* d_out, int out_size) {
    const float* x      = (const float*)d_in[0];
    const float* gate_w = (const float*)d_in[1];
    const float* gate_b = (const float*)d_in[2];
    const float* W1     = (const float*)d_in[3];
    const float* W3     = (const float*)d_in[4];
    const float* W2     = (const float*)d_in[5];
    const float* Ws1    = (const float*)d_in[6];
    const float* Ws3    = (const float*)d_in[7];
    const float* Ws2    = (const float*)d_in[8];
    float* out = (float*)d_out;

    cudaFuncSetAttribute(gemm1_tc, cudaFuncAttributeMaxDynamicSharedMemorySize, SMEM1_TOTAL);
    cudaFuncSetAttribute(gemm2_tc, cudaFuncAttributeMaxDynamicSharedMemorySize, SMEM2_TOTAL);

    gate_kernel<<<TT / 8, 256>>>(x, gate_w, gate_b);
    gemm1_tc<<<dim3(16, 16, 9), 256, SMEM1_TOTAL>>>(x, W1, W3, Ws1, Ws3);
    gemm2_tc<<<dim3(16, 16, 9), 256, SMEM2_TOTAL>>>(W2, Ws2);
    combine_kernel<<<TT / 8, 256>>>(out);
}